// round 9
// baseline (speedup 1.0000x reference)
#include <cuda_runtime.h>
#include <cuda_fp16.h>
#include <math.h>
#include <stdint.h>

#define BB 16
#define LL 1024
#define MM 21
#define PP 16
#define NN 64
#define DD 768
#define HH 8
#define EE 96
#define FF4 3072
#define NLAYER 3
#define FREQ 33
#define A2 32
#define PREDN 96
#define BMC (BB*MM)          /* 336 */
#define ROWS (BMC*NN)        /* 21504 */
#define EPSF 1e-5f
#define QKVS 2304

/* ---------------- scratch layout (float units) ---------------- */
#define OFF_MEAN   0u
#define OFF_STD    512u
#define OFF_PATCH  1024u
#define OFF_T      345088u
#define OFF_MU     357376u
#define OFF_RV     373760u
#define OFF_AD     390144u
#define OFF_BNSUM  734208u
#define OFF_BNSQ   734976u
#define OFF_OSMALL 735744u
#define OFF_H      768000u
#define OFF_Y      (OFF_H + 16515072u)
#define OFF_QKVH   (OFF_Y + 16515072u)          /* ROWS*2304 halfs = 24772608 fl */
#define OFF_SC     (OFF_QKVH + 24772608u)
#define OFF_Y16    (OFF_SC + 11010048u)
#define OFF_O16    (OFF_Y16 + 8257536u)
#define OFF_F4H    (OFF_O16 + 8257536u)
#define OFF_WH     (OFF_F4H + 33030144u)
#define OFF_BQKV   (OFF_WH + 10616832u)
#define TOTAL_F    (OFF_BQKV + 8192u)

__device__ float g_buf[TOTAL_F];

/* ================= helpers ================= */
__device__ __forceinline__ uint32_t s2u(const void* p) {
    uint32_t a;
    asm("{ .reg .u64 t; cvta.to.shared.u64 t, %1; cvt.u32.u64 %0, t; }" : "=r"(a) : "l"(p));
    return a;
}
__device__ __forceinline__ void mma_f16(float* d, const unsigned* a, const unsigned* b) {
    asm volatile("mma.sync.aligned.m16n8k16.row.col.f32.f16.f16.f32 "
                 "{%0,%1,%2,%3},{%4,%5,%6,%7},{%8,%9},{%0,%1,%2,%3};"
                 : "+f"(d[0]), "+f"(d[1]), "+f"(d[2]), "+f"(d[3])
                 : "r"(a[0]), "r"(a[1]), "r"(a[2]), "r"(a[3]), "r"(b[0]), "r"(b[1]));
}
__device__ __forceinline__ void cp16(uint32_t saddr, const void* g) {
    asm volatile("cp.async.ca.shared.global [%0], [%1], 16;" :: "r"(saddr), "l"(g));
}

/* ---------------- weight fp16 conversion ---------------- */
__global__ void wconv_h_kernel(const float* __restrict__ in, __half* __restrict__ out, int n) {
    int idx = blockIdx.x * 256 + threadIdx.x;
    if (idx < n) out[idx] = __float2half(in[idx]);
}
__global__ void wconv_qkv_h_kernel(const float* __restrict__ in, __half* __restrict__ out,
                                   int part) {
    int idx = blockIdx.x * 256 + threadIdx.x;
    int lay = idx / 589824, w = idx % 589824;
    out[(size_t)lay * 1769472 + (size_t)part * 589824 + w] = __float2half(in[idx]);
}
__global__ void bpack_kernel(const float* __restrict__ bq, const float* __restrict__ bk,
                             const float* __restrict__ bv, float* __restrict__ out) {
    int idx = blockIdx.x * 256 + threadIdx.x;
    if (idx >= NLAYER * QKVS) return;
    int lay = idx / QKVS, c = idx % QKVS;
    float v;
    if (c < 768) v = bq[lay * 768 + c];
    else if (c < 1536) v = bk[lay * 768 + c - 768];
    else v = bv[lay * 768 + c - 1536];
    out[idx] = v;
}

/* =========== cp.async 4-stage fp16 mma GEMM (+optional bn-stats epilogue) ===== */
#define STAGES 4
#define HSTG   10240
#define GSMH   (STAGES * HSTG * 2)         /* 81920 bytes */

template<int RELU, int RES, int OUTH, int STATS>
__global__ __launch_bounds__(128, 2) void hgemm(const __half* __restrict__ A,
                                                const __half* __restrict__ W,
                                                const float* __restrict__ bias,
                                                const float* __restrict__ Rsrc,
                                                void* __restrict__ Cv,
                                                float* __restrict__ gsum,
                                                float* __restrict__ gsq,
                                                int M, int N, int K) {
    extern __shared__ __half hsm[];
    const int t = threadIdx.x;
    const int wid = t >> 5, lane = t & 31;
    const int wm = wid >> 1, wn = wid & 1;
    const int m0 = blockIdx.y * 128, n0 = blockIdx.x * 128;
    const int fr = lane >> 2, fc = lane & 3;

    const __half* Agp = A + (size_t)m0 * K;
    const __half* Bgp = W + (size_t)n0 * K;

    float acc[4][8][4];
#pragma unroll
    for (int i = 0; i < 4; ++i)
#pragma unroll
        for (int j = 0; j < 8; ++j)
#pragma unroll
            for (int r = 0; r < 4; ++r) acc[i][j][r] = 0.f;

    const int NT = K >> 5;

#pragma unroll
    for (int s = 0; s < STAGES - 1; ++s) {
        __half* st = hsm + s * HSTG;
        const __half* Ag = Agp + s * 32;
        const __half* Bg = Bgp + s * 32;
#pragma unroll
        for (int j = 0; j < 4; ++j) {
            int id = t + j * 128;
            int row = id >> 2, c8 = (id & 3) * 8;
            cp16(s2u(st + row * 40 + c8), Ag + (size_t)row * K + c8);
            cp16(s2u(st + 5120 + row * 40 + c8), Bg + (size_t)row * K + c8);
        }
        asm volatile("cp.async.commit_group;");
    }

    for (int kb = 0; kb < NT; ++kb) {
        asm volatile("cp.async.wait_group %0;" :: "n"(STAGES - 2));
        __syncthreads();
        if (kb + STAGES - 1 < NT) {
            __half* st = hsm + ((kb + STAGES - 1) & (STAGES - 1)) * HSTG;
            const __half* Ag = Agp + (kb + STAGES - 1) * 32;
            const __half* Bg = Bgp + (kb + STAGES - 1) * 32;
#pragma unroll
            for (int j = 0; j < 4; ++j) {
                int id = t + j * 128;
                int row = id >> 2, c8 = (id & 3) * 8;
                cp16(s2u(st + row * 40 + c8), Ag + (size_t)row * K + c8);
                cp16(s2u(st + 5120 + row * 40 + c8), Bg + (size_t)row * K + c8);
            }
        }
        asm volatile("cp.async.commit_group;");

        const __half* Ab = hsm + (kb & (STAGES - 1)) * HSTG;
        const __half* Bb = Ab + 5120;
#pragma unroll
        for (int ks = 0; ks < 2; ++ks) {
            const int k0 = ks * 16;
            unsigned af[4][4], bf[8][2];
#pragma unroll
            for (int mt = 0; mt < 4; ++mt) {
                int row = wm * 64 + mt * 16 + fr;
                af[mt][0] = *(const uint32_t*)&Ab[row * 40 + k0 + 2 * fc];
                af[mt][1] = *(const uint32_t*)&Ab[(row + 8) * 40 + k0 + 2 * fc];
                af[mt][2] = *(const uint32_t*)&Ab[row * 40 + k0 + 2 * fc + 8];
                af[mt][3] = *(const uint32_t*)&Ab[(row + 8) * 40 + k0 + 2 * fc + 8];
            }
#pragma unroll
            for (int nt = 0; nt < 8; ++nt) {
                int col = wn * 64 + nt * 8 + fr;
                bf[nt][0] = *(const uint32_t*)&Bb[col * 40 + k0 + 2 * fc];
                bf[nt][1] = *(const uint32_t*)&Bb[col * 40 + k0 + 2 * fc + 8];
            }
#pragma unroll
            for (int mt = 0; mt < 4; ++mt)
#pragma unroll
                for (int nt = 0; nt < 8; ++nt)
                    mma_f16(acc[mt][nt], af[mt], bf[nt]);
        }
    }

    float* scol = (float*)hsm;     /* stage memory reused post-mainloop */
    if (STATS) {
        __syncthreads();
        scol[t] = 0.f; scol[t + 128] = 0.f;
        __syncthreads();
    }

    const int c2 = (lane & 3) * 2;
    float cs[16], cq[16];
    if (STATS) {
#pragma unroll
        for (int i = 0; i < 16; ++i) { cs[i] = 0.f; cq[i] = 0.f; }
    }
#pragma unroll
    for (int mt = 0; mt < 4; ++mt) {
        int row = m0 + wm * 64 + mt * 16 + fr;
#pragma unroll
        for (int nt = 0; nt < 8; ++nt) {
            int col = n0 + wn * 64 + nt * 8 + c2;
            size_t i0 = (size_t)row * N + col;
            size_t i1 = (size_t)(row + 8) * N + col;
            float b0 = bias[col], b1 = bias[col + 1];
            float v0 = acc[mt][nt][0] + b0, v1 = acc[mt][nt][1] + b1;
            float v2 = acc[mt][nt][2] + b0, v3 = acc[mt][nt][3] + b1;
            if (RES) {
                float2 r0 = *(const float2*)&Rsrc[i0];
                float2 r1 = *(const float2*)&Rsrc[i1];
                v0 += r0.x; v1 += r0.y; v2 += r1.x; v3 += r1.y;
            }
            if (RELU) { v0 = fmaxf(v0, 0.f); v1 = fmaxf(v1, 0.f); v2 = fmaxf(v2, 0.f); v3 = fmaxf(v3, 0.f); }
            if (STATS) {
                cs[nt * 2]     += v0 + v2;  cq[nt * 2]     += v0 * v0 + v2 * v2;
                cs[nt * 2 + 1] += v1 + v3;  cq[nt * 2 + 1] += v1 * v1 + v3 * v3;
            }
            if (OUTH) {
                __half* Ch = (__half*)Cv;
                *(__half2*)(Ch + i0) = __floats2half2_rn(v0, v1);
                *(__half2*)(Ch + i1) = __floats2half2_rn(v2, v3);
            } else {
                float* Cf = (float*)Cv;
                float2 o0 = {v0, v1}, o1 = {v2, v3};
                *(float2*)&Cf[i0] = o0;
                *(float2*)&Cf[i1] = o1;
            }
        }
    }
    if (STATS) {
#pragma unroll
        for (int nt = 0; nt < 8; ++nt) {
            int cloc = wn * 64 + nt * 8 + c2;
            atomicAdd(&scol[cloc], cs[nt * 2]);
            atomicAdd(&scol[128 + cloc], cq[nt * 2]);
            atomicAdd(&scol[cloc + 1], cs[nt * 2 + 1]);
            atomicAdd(&scol[128 + cloc + 1], cq[nt * 2 + 1]);
        }
        __syncthreads();
        atomicAdd(&gsum[n0 + t], scol[t]);
        atomicAdd(&gsq[n0 + t], scol[128 + t]);
    }
}

/* ---------------- RevIN stats ---------------- */
__global__ void revin_stats_kernel(const float* __restrict__ x, float* __restrict__ mean,
                                   float* __restrict__ stdv) {
    int bm = blockIdx.x;
    int b = bm / MM, m = bm % MM;
    const float* xp = x + (size_t)b * LL * MM + m;
    float s = 0.f, s2 = 0.f;
    for (int l = threadIdx.x; l < LL; l += 256) {
        float v = xp[(size_t)l * MM];
        s += v; s2 += v * v;
    }
    __shared__ float sh0[256], sh1[256];
    sh0[threadIdx.x] = s; sh1[threadIdx.x] = s2;
    __syncthreads();
    for (int off = 128; off > 0; off >>= 1) {
        if (threadIdx.x < off) { sh0[threadIdx.x] += sh0[threadIdx.x + off]; sh1[threadIdx.x] += sh1[threadIdx.x + off]; }
        __syncthreads();
    }
    if (threadIdx.x == 0) {
        float mu = sh0[0] * (1.f / LL);
        float var = sh1[0] * (1.f / LL) - mu * mu;
        mean[bm] = mu;
        stdv[bm] = sqrtf(var + EPSF);
    }
}

/* ---------------- patches ---------------- */
__global__ void patches_kernel(const float* __restrict__ x, const float* __restrict__ mean,
                               const float* __restrict__ stdv, const float* __restrict__ rw,
                               const float* __restrict__ rb, float* __restrict__ patches) {
    int idx = blockIdx.x * 256 + threadIdx.x;
    int p = idx & 15;
    int n = (idx >> 4) & 63;
    int bm = idx >> 10;
    int m = bm % MM;
    int b = bm / MM;
    int l = n * 16 + p;
    float v = x[(size_t)b * LL * MM + (size_t)l * MM + m];
    v = (v - mean[bm]) / stdv[bm] * rw[m] + rb[m];
    patches[idx] = v;
}

/* ---------------- composed spectral transform ---------------- */
__global__ void computeT_kernel(const float* __restrict__ wr, const float* __restrict__ wi,
                                float* __restrict__ T) {
    int lay = blockIdx.x;
    __shared__ float Ur[32][64], Ui[32][64];
    const float* wrp = wr + (size_t)lay * FREQ * A2;
    const float* wip = wi + (size_t)lay * FREQ * A2;
    const float c0 = 6.28318530717958647692f / 64.f;
    for (int e = threadIdx.x; e < 32 * 64; e += 256) {
        int d = e >> 6, n = e & 63;
        float sr = 0.f, si = 0.f;
        for (int kf = 0; kf < FREQ; ++kf) {
            float ang = c0 * (float)(kf * n);
            float cv, sv;
            sincosf(ang, &sv, &cv);
            sr += wrp[kf * A2 + d] * cv;
            si += wip[kf * A2 + d] * (-sv);
        }
        Ur[d][n] = sr; Ui[d][n] = si;
    }
    __syncthreads();
    for (int e = threadIdx.x; e < 64 * 64; e += 256) {
        int a = e >> 6, n = e & 63;
        float tval = Ur[0][n];
        for (int d = 1; d < 32; ++d) {
            float ang = c0 * (float)(d * a);
            float cv, sv;
            sincosf(ang, &sv, &cv);
            tval += 2.f * (Ur[d][n] * cv - Ui[d][n] * sv);
        }
        T[lay * 4096 + e] = tval * (1.f / 64.f);
    }
}

/* ---------------- instance-norm stats ---------------- */
__global__ void pn_stats_kernel(const float* __restrict__ patches, float* __restrict__ mu,
                                float* __restrict__ rv) {
    int idx = blockIdx.x * 256 + threadIdx.x;
    int b = idx >> 10;
    int np = idx & 1023;
    const float* pp = patches + (size_t)b * 21504 + np;
    float s = 0.f, s2 = 0.f;
#pragma unroll
    for (int m = 0; m < MM; ++m) { float v = pp[m * 1024]; s += v; s2 += v * v; }
    float m0 = s * (1.f / MM);
    float var = s2 * (1.f / MM) - m0 * m0;
    mu[idx] = m0;
    rv[idx] = rsqrtf(var + EPSF);
}

/* ---------------- spectral mixing ---------------- */
__global__ void spect_kernel(const float* __restrict__ patches, const float* __restrict__ mu,
                             const float* __restrict__ rv, const float* __restrict__ g,
                             const float* __restrict__ be, const float* __restrict__ T,
                             float* __restrict__ ad) {
    int idx = blockIdx.x * 256 + threadIdx.x;
    int p = idx & 15;
    int a = (idx >> 4) & 63;
    int bm = idx >> 10;
    int m = bm % MM;
    int b = bm / MM;
    float gm = g[m], bm_ = be[m];
    const float* pp  = patches + (size_t)bm * 1024 + p;
    const float* mup = mu + b * 1024 + p;
    const float* rvp = rv + b * 1024 + p;
    const float* Tp  = T + a * 64;
    float acc = 0.f;
#pragma unroll 8
    for (int n = 0; n < 64; ++n) {
        float pn = (pp[n * 16] - mup[n * 16]) * rvp[n * 16] * gm + bm_;
        acc += Tp[n] * pn;
    }
    ad[idx] = acc;
}

/* ---------------- embeddings ---------------- */
template<int ADD>
__global__ __launch_bounds__(256) void embed_kernel(const float* __restrict__ src,
                                                    const float* __restrict__ Hin,
                                                    const float* __restrict__ inw,
                                                    const float* __restrict__ inb,
                                                    float* __restrict__ out32,
                                                    __half* __restrict__ out16) {
    __shared__ float ps[1024];
    int blk = blockIdx.x;
    int t = threadIdx.x;
    const float4* sp = (const float4*)(src + (size_t)blk * 1024);
    ((float4*)ps)[t] = sp[t];
    float w[3][16], bb[3];
#pragma unroll
    for (int j = 0; j < 3; ++j) {
        int c = t + 256 * j;
        bb[j] = inb[c];
#pragma unroll
        for (int p4 = 0; p4 < 4; ++p4) {
            float4 wv = *(const float4*)(inw + (size_t)c * 16 + p4 * 4);
            w[j][p4 * 4] = wv.x; w[j][p4 * 4 + 1] = wv.y; w[j][p4 * 4 + 2] = wv.z; w[j][p4 * 4 + 3] = wv.w;
        }
    }
    __syncthreads();
    size_t rowbase = (size_t)blk * 64 * DD;
    for (int r = 0; r < 64; ++r) {
        float pr[16];
#pragma unroll
        for (int p4 = 0; p4 < 4; ++p4) {
            float4 pv = *(const float4*)&ps[r * 16 + p4 * 4];
            pr[p4 * 4] = pv.x; pr[p4 * 4 + 1] = pv.y; pr[p4 * 4 + 2] = pv.z; pr[p4 * 4 + 3] = pv.w;
        }
        size_t ro = rowbase + (size_t)r * DD;
#pragma unroll
        for (int j = 0; j < 3; ++j) {
            float acc = bb[j];
            if (ADD) acc += Hin[ro + t + 256 * j];
#pragma unroll
            for (int p = 0; p < 16; ++p) acc = fmaf(pr[p], w[j][p], acc);
            out32[ro + t + 256 * j] = acc;
            if (ADD) out16[ro + t + 256 * j] = __float2half(acc);
        }
    }
}

/* ---------------- attention: fused scores + bias + softmax (half qkv) --------- */
__global__ __launch_bounds__(256) void scores_softmax_kernel(const __half* __restrict__ qkv,
                                                             const float* __restrict__ bias,
                                                             float* __restrict__ sc) {
    int bm = blockIdx.x, h = blockIdx.y;
    __shared__ float qs[64 * 96];
    __shared__ float ksT[96 * 68];
    int t = threadIdx.x;
    const __half* qg = qkv + (size_t)bm * 64 * QKVS + h * EE;
    const __half* kg = qkv + (size_t)bm * 64 * QKVS + 768 + h * EE;
    for (int i = t; i < 768; i += 256) {
        int r = i / 12, c = i % 12;
        uint4 raw = *(const uint4*)(qg + (size_t)r * QKVS + c * 8);
        const __half2* hp = (const __half2*)&raw;
        float* dst = &qs[r * 96 + c * 8];
        float2 f0 = __half22float2(hp[0]), f1 = __half22float2(hp[1]);
        float2 f2 = __half22float2(hp[2]), f3 = __half22float2(hp[3]);
        dst[0] = f0.x; dst[1] = f0.y; dst[2] = f1.x; dst[3] = f1.y;
        dst[4] = f2.x; dst[5] = f2.y; dst[6] = f3.x; dst[7] = f3.y;
    }
    for (int i = t; i < 768; i += 256) {
        int s = i / 12, c = i % 12;
        uint4 raw = *(const uint4*)(kg + (size_t)s * QKVS + c * 8);
        const __half2* hp = (const __half2*)&raw;
        float2 f0 = __half22float2(hp[0]), f1 = __half22float2(hp[1]);
        float2 f2 = __half22float2(hp[2]), f3 = __half22float2(hp[3]);
        ksT[(c * 8 + 0) * 68 + s] = f0.x; ksT[(c * 8 + 1) * 68 + s] = f0.y;
        ksT[(c * 8 + 2) * 68 + s] = f1.x; ksT[(c * 8 + 3) * 68 + s] = f1.y;
        ksT[(c * 8 + 4) * 68 + s] = f2.x; ksT[(c * 8 + 5) * 68 + s] = f2.y;
        ksT[(c * 8 + 6) * 68 + s] = f3.x; ksT[(c * 8 + 7) * 68 + s] = f3.y;
    }
    __syncthreads();
    int l0 = (t >> 4) * 4, s0 = (t & 15) * 4;
    float acc[4][4] = {};
    for (int e = 0; e < 96; ++e) {
        float4 kv = *(const float4*)&ksT[e * 68 + s0];
#pragma unroll
        for (int i2 = 0; i2 < 4; ++i2) {
            float qv = qs[(l0 + i2) * 96 + e];
            acc[i2][0] = fmaf(qv, kv.x, acc[i2][0]);
            acc[i2][1] = fmaf(qv, kv.y, acc[i2][1]);
            acc[i2][2] = fmaf(qv, kv.z, acc[i2][2]);
            acc[i2][3] = fmaf(qv, kv.w, acc[i2][3]);
        }
    }
    const float SCALE = 0.10206207261596575f;
    float* scp = sc + (size_t)(bm * 8 + h) * 4096;
#pragma unroll
    for (int i2 = 0; i2 < 4; ++i2) {
        int l = l0 + i2;
        float v[4];
#pragma unroll
        for (int j = 0; j < 4; ++j)
            v[j] = acc[i2][j] * SCALE + bias[(l * 64 + s0 + j) * 8 + h];
        float mx = fmaxf(fmaxf(v[0], v[1]), fmaxf(v[2], v[3]));
#pragma unroll
        for (int off = 8; off > 0; off >>= 1)
            mx = fmaxf(mx, __shfl_xor_sync(0xffffffffu, mx, off, 16));
        float sum = 0.f;
#pragma unroll
        for (int j = 0; j < 4; ++j) { v[j] = expf(v[j] - mx); sum += v[j]; }
#pragma unroll
        for (int off = 8; off > 0; off >>= 1)
            sum += __shfl_xor_sync(0xffffffffu, sum, off, 16);
        float inv = 1.f / sum;
        float4 o4 = {v[0] * inv, v[1] * inv, v[2] * inv, v[3] * inv};
        *(float4*)&scp[l * 64 + s0] = o4;
    }
}

/* ---------------- attention: tiled AV (half qkv in, half out) ---------------- */
__global__ __launch_bounds__(256) void av_tile_kernel(const float* __restrict__ sc,
                                                      const __half* __restrict__ qkv,
                                                      __half* __restrict__ o) {
    int bm = blockIdx.x, h = blockIdx.y;
    __shared__ float at[64 * 65];
    __shared__ float vs[64 * 96];
    int t = threadIdx.x;
    const float* ap = sc + (size_t)(bm * 8 + h) * 4096;
    const __half* vg = qkv + (size_t)bm * 64 * QKVS + 1536 + h * EE;
    for (int i = t; i < 1024; i += 256) {
        int l = i >> 4, c = i & 15;
        float4 a4 = *(const float4*)(ap + l * 64 + c * 4);
        at[l * 65 + c * 4 + 0] = a4.x; at[l * 65 + c * 4 + 1] = a4.y;
        at[l * 65 + c * 4 + 2] = a4.z; at[l * 65 + c * 4 + 3] = a4.w;
    }
    for (int i = t; i < 768; i += 256) {
        int s = i / 12, c = i % 12;
        uint4 raw = *(const uint4*)(vg + (size_t)s * QKVS + c * 8);
        const __half2* hp = (const __half2*)&raw;
        float* dst = &vs[s * 96 + c * 8];
        float2 f0 = __half22float2(hp[0]), f1 = __half22float2(hp[1]);
        float2 f2 = __half22float2(hp[2]), f3 = __half22float2(hp[3]);
        dst[0] = f0.x; dst[1] = f0.y; dst[2] = f1.x; dst[3] = f1.y;
        dst[4] = f2.x; dst[5] = f2.y; dst[6] = f3.x; dst[7] = f3.y;
    }
    __syncthreads();
    int l0 = (t >> 4) * 4, e0 = (t & 15) * 6;
    float acc[4][6] = {};
    for (int s = 0; s < 64; ++s) {
        float av_[4], vv[6];
#pragma unroll
        for (int i2 = 0; i2 < 4; ++i2) av_[i2] = at[(l0 + i2) * 65 + s];
#pragma unroll
        for (int j = 0; j < 6; ++j) vv[j] = vs[s * 96 + e0 + j];
#pragma unroll
        for (int i2 = 0; i2 < 4; ++i2)
#pragma unroll
            for (int j = 0; j < 6; ++j) acc[i2][j] = fmaf(av_[i2], vv[j], acc[i2][j]);
    }
    __half* op = o + (size_t)bm * 64 * DD + h * EE;
#pragma unroll
    for (int i2 = 0; i2 < 4; ++i2)
#pragma unroll
        for (int j = 0; j < 6; ++j)
            op[(size_t)(l0 + i2) * DD + e0 + j] = __float2half(acc[i2][j]);
}

/* ---------------- batchnorm apply ---------------- */
__global__ void zero_kernel(float* __restrict__ p, int n) {
    int idx = blockIdx.x * 256 + threadIdx.x;
    if (idx < n) p[idx] = 0.f;
}

template<int WH>
__global__ void bn_apply_kernel(float* __restrict__ X, const float* __restrict__ sum,
                                const float* __restrict__ sq, const float* __restrict__ g,
                                const float* __restrict__ be, __half* __restrict__ Xh) {
    int idx = blockIdx.x * 256 + threadIdx.x;
    int c = idx % DD;
    const float inv_n = 1.f / (float)ROWS;
    float mean = sum[c] * inv_n;
    float var = sq[c] * inv_n - mean * mean;
    float v = (X[idx] - mean) * rsqrtf(var + EPSF) * g[c] + be[c];
    X[idx] = v;
    if (WH) Xh[idx] = __float2half(v);
}

/* fused bn2 + final norm (layer 3): bn3(bn2(X)) from X's stats */
__global__ void bn_apply_final_kernel(float* __restrict__ X, const float* __restrict__ sum,
                                      const float* __restrict__ sq,
                                      const float* __restrict__ g2, const float* __restrict__ b2,
                                      const float* __restrict__ g3, const float* __restrict__ b3) {
    int idx = blockIdx.x * 256 + threadIdx.x;
    int c = idx % DD;
    const float inv_n = 1.f / (float)ROWS;
    float mean = sum[c] * inv_n;
    float var = sq[c] * inv_n - mean * mean;
    float r = rsqrtf(var + EPSF);
    float s = g2[c] * r;
    float xv = (X[idx] - mean) * s;                 /* = bn2(X) - b2 */
    float r2 = rsqrtf(s * s * var + EPSF);
    X[idx] = xv * r2 * g3[c] + b3[c];
}

/* ---------------- final projection ---------------- */
__global__ void final_gemm_kernel(const float* __restrict__ hbuf, const float* __restrict__ ow,
                                  float* __restrict__ osmall) {
    __shared__ float hs[8 * 1024];
    int row0 = blockIdx.x * 8;
    int k0 = blockIdx.y * 1024;
    for (int j = threadIdx.x; j < 2048; j += 128) {
        int r = j >> 8, kq = j & 255;
        *(float4*)&hs[r * 1024 + kq * 4] =
            *(const float4*)&hbuf[(size_t)(row0 + r) * 49152 + k0 + kq * 4];
    }
    __syncthreads();
    int p = threadIdx.x;
    if (p < PREDN) {
        float acc[8] = {0.f, 0.f, 0.f, 0.f, 0.f, 0.f, 0.f, 0.f};
        const float* wp = ow + (size_t)p * 49152 + k0;
        for (int kq = 0; kq < 256; ++kq) {
            float4 w4 = *(const float4*)(wp + kq * 4);
#pragma unroll
            for (int r = 0; r < 8; ++r) {
                const float* hr = &hs[r * 1024 + kq * 4];
                acc[r] += hr[0] * w4.x + hr[1] * w4.y + hr[2] * w4.z + hr[3] * w4.w;
            }
        }
#pragma unroll
        for (int r = 0; r < 8; ++r) atomicAdd(&osmall[(row0 + r) * PREDN + p], acc[r]);
    }
}

/* ---------------- de-norm ---------------- */
__global__ void denorm_kernel(const float* __restrict__ osmall, const float* __restrict__ outb,
                              const float* __restrict__ rw, const float* __restrict__ rb,
                              const float* __restrict__ mean, const float* __restrict__ stdv,
                              float* __restrict__ out) {
    int idx = blockIdx.x * 256 + threadIdx.x;
    int m = idx % MM;
    int pr = (idx / MM) % PREDN;
    int b = idx / (MM * PREDN);
    int bm = b * MM + m;
    float v = osmall[bm * PREDN + pr] + outb[pr];
    v = (v - rb[m]) / (rw[m] + 1e-10f);
    out[idx] = v * stdv[bm] + mean[bm];
}

/* ---------------- launcher ---------------- */
extern "C" void kernel_launch(void* const* d_in, const int* in_sizes, int n_in,
                              void* d_out, int out_size) {
    const float* x         = (const float*)d_in[0];
    const float* attn_bias = (const float*)d_in[1];
    const float* revin_w   = (const float*)d_in[2];
    const float* revin_b   = (const float*)d_in[3];
    const float* in_w      = (const float*)d_in[4];
    const float* in_b      = (const float*)d_in[5];
    const float* ln1_g     = (const float*)d_in[6];
    const float* ln1_b     = (const float*)d_in[7];
    const float* spect_wr  = (const float*)d_in[8];
    const float* spect_wi  = (const float*)d_in[9];
    const float* Wq        = (const float*)d_in[10];
    const float* bq        = (const float*)d_in[11];
    const float* Wk        = (const float*)d_in[12];
    const float* bk        = (const float*)d_in[13];
    const float* Wv        = (const float*)d_in[14];
    const float* bv        = (const float*)d_in[15];
    const float* Wo        = (const float*)d_in[16];
    const float* bo        = (const float*)d_in[17];
    const float* c1_w      = (const float*)d_in[18];
    const float* c1_b      = (const float*)d_in[19];
    const float* c2_w      = (const float*)d_in[20];
    const float* c2_b      = (const float*)d_in[21];
    const float* bn1_g     = (const float*)d_in[22];
    const float* bn1_b     = (const float*)d_in[23];
    const float* bn2_g     = (const float*)d_in[24];
    const float* bn2_b     = (const float*)d_in[25];
    const float* norm_g    = (const float*)d_in[26];
    const float* norm_b    = (const float*)d_in[27];
    const float* out_w     = (const float*)d_in[28];
    const float* out_b     = (const float*)d_in[29];

    float* base = nullptr;
    cudaGetSymbolAddress((void**)&base, g_buf);
    float* mean   = base + OFF_MEAN;
    float* stdv   = base + OFF_STD;
    float* patch  = base + OFF_PATCH;
    float* Tm     = base + OFF_T;
    float* mu     = base + OFF_MU;
    float* rv     = base + OFF_RV;
    float* ad     = base + OFF_AD;
    float* bnsum  = base + OFF_BNSUM;
    float* bnsq   = base + OFF_BNSQ;
    float* osmall = base + OFF_OSMALL;
    float* h      = base + OFF_H;
    float* y      = base + OFF_Y;
    __half* qkvh  = (__half*)(base + OFF_QKVH);
    float* sc     = base + OFF_SC;
    __half* y16   = (__half*)(base + OFF_Y16);
    __half* o16   = (__half*)(base + OFF_O16);
    __half* f4h   = (__half*)(base + OFF_F4H);
    __half* wh    = (__half*)(base + OFF_WH);
    __half* WHqkv = wh;
    __half* WHo   = wh + 5308416u;
    __half* WH1   = wh + 7077888u;
    __half* WH2   = wh + 14155776u;
    float* bqkv   = base + OFF_BQKV;

    cudaFuncSetAttribute(hgemm<0, 0, 1, 0>, cudaFuncAttributeMaxDynamicSharedMemorySize, GSMH);
    cudaFuncSetAttribute(hgemm<0, 1, 0, 1>, cudaFuncAttributeMaxDynamicSharedMemorySize, GSMH);
    cudaFuncSetAttribute(hgemm<1, 0, 1, 0>, cudaFuncAttributeMaxDynamicSharedMemorySize, GSMH);

    const int TPB = 256;
    const int G_ED = (ROWS * DD) / TPB;

    wconv_qkv_h_kernel<<<1769472 / TPB, TPB>>>(Wq, WHqkv, 0);
    wconv_qkv_h_kernel<<<1769472 / TPB, TPB>>>(Wk, WHqkv, 1);
    wconv_qkv_h_kernel<<<1769472 / TPB, TPB>>>(Wv, WHqkv, 2);
    wconv_h_kernel<<<1769472 / TPB, TPB>>>(Wo, WHo, 1769472);
    wconv_h_kernel<<<7077888 / TPB, TPB>>>(c1_w, WH1, 7077888);
    wconv_h_kernel<<<7077888 / TPB, TPB>>>(c2_w, WH2, 7077888);
    bpack_kernel<<<27, TPB>>>(bq, bk, bv, bqkv);

    revin_stats_kernel<<<BMC, TPB>>>(x, mean, stdv);
    patches_kernel<<<344064 / TPB, TPB>>>(x, mean, stdv, revin_w, revin_b, patch);
    computeT_kernel<<<NLAYER, TPB>>>(spect_wr, spect_wi, Tm);
    embed_kernel<0><<<BMC, TPB>>>(patch, nullptr, in_w, in_b, h, nullptr);

    dim3 gQKV(QKVS / 128, ROWS / 128);
    dim3 gP(DD / 128, ROWS / 128);
    dim3 gF1(FF4 / 128, ROWS / 128);
    dim3 gS(BMC, HH);
    dim3 gAV(BMC, HH);

    for (int i = 0; i < NLAYER; ++i) {
        pn_stats_kernel<<<16384 / TPB, TPB>>>(patch, mu, rv);
        spect_kernel<<<344064 / TPB, TPB>>>(patch, mu, rv, ln1_g + i * MM, ln1_b + i * MM,
                                            Tm + i * 4096, ad);
        embed_kernel<1><<<BMC, TPB>>>(ad, h, in_w, in_b, y, y16);

        hgemm<0, 0, 1, 0><<<gQKV, 128, GSMH>>>(y16, WHqkv + (size_t)i * 1769472u,
                                               bqkv + i * QKVS, nullptr, qkvh,
                                               nullptr, nullptr, ROWS, QKVS, DD);

        scores_softmax_kernel<<<gS, TPB>>>(qkvh, attn_bias, sc);
        av_tile_kernel<<<gAV, TPB>>>(sc, qkvh, o16);

        zero_kernel<<<6, TPB>>>(bnsum, 1536);
        hgemm<0, 1, 0, 1><<<gP, 128, GSMH>>>(o16, WHo + (size_t)i * DD * DD, bo + i * DD,
                                             y, y, bnsum, bnsq, ROWS, DD, DD);
        bn_apply_kernel<1><<<G_ED, TPB>>>(y, bnsum, bnsq, bn1_g + i * DD, bn1_b + i * DD, y16);

        hgemm<1, 0, 1, 0><<<gF1, 128, GSMH>>>(y16, WH1 + (size_t)i * FF4 * DD, c1_b + i * FF4,
                                              nullptr, f4h, nullptr, nullptr, ROWS, FF4, DD);
        zero_kernel<<<6, TPB>>>(bnsum, 1536);
        hgemm<0, 1, 0, 1><<<gP, 128, GSMH>>>(f4h, WH2 + (size_t)i * DD * FF4, c2_b + i * DD,
                                             y, h, bnsum, bnsq, ROWS, DD, FF4);

        if (i < NLAYER - 1) {
            bn_apply_kernel<0><<<G_ED, TPB>>>(h, bnsum, bnsq, bn2_g + i * DD, bn2_b + i * DD, nullptr);
        } else {
            bn_apply_final_kernel<<<G_ED, TPB>>>(h, bnsum, bnsq, bn2_g + i * DD, bn2_b + i * DD,
                                                 norm_g, norm_b);
        }
    }

    zero_kernel<<<32256 / TPB, TPB>>>(osmall, 32256);
    final_gemm_kernel<<<dim3(BMC / 8, 48), 128>>>(h, out_w, osmall);
    denorm_kernel<<<32256 / TPB, TPB>>>(osmall, out_b, revin_w, revin_b, mean, stdv,
                                        (float*)d_out);
}

// round 10
// speedup vs baseline: 1.0412x; 1.0412x over previous
#include <cuda_runtime.h>
#include <cuda_fp16.h>
#include <math.h>
#include <stdint.h>

#define BB 16
#define LL 1024
#define MM 21
#define PP 16
#define NN 64
#define DD 768
#define HH 8
#define EE 96
#define FF4 3072
#define NLAYER 3
#define FREQ 33
#define A2 32
#define PREDN 96
#define BMC (BB*MM)          /* 336 */
#define ROWS (BMC*NN)        /* 21504 */
#define EPSF 1e-5f
#define QKVS 2304

/* ---------------- scratch layout (float units) ---------------- */
#define OFF_MEAN   0u
#define OFF_STD    512u
#define OFF_PATCH  1024u
#define OFF_T      345088u
#define OFF_MU     357376u
#define OFF_RV     373760u
#define OFF_AD     390144u
#define OFF_BNSUM  734208u
#define OFF_BNSQ   734976u
#define OFF_OSMALL 735744u
#define OFF_H      768000u
#define OFF_Y      (OFF_H + 16515072u)
#define OFF_QKVH   (OFF_Y + 16515072u)          /* ROWS*2304 halfs */
#define OFF_SC     (OFF_QKVH + 24772608u)
#define OFF_Y16    (OFF_SC + 11010048u)
#define OFF_O16    (OFF_Y16 + 8257536u)
#define OFF_F4H    (OFF_O16 + 8257536u)
#define OFF_WH     (OFF_F4H + 33030144u)
#define OFF_BQKV   (OFF_WH + 10616832u)
#define TOTAL_F    (OFF_BQKV + 8192u)

__device__ float g_buf[TOTAL_F];

/* ================= helpers ================= */
__device__ __forceinline__ uint32_t s2u(const void* p) {
    uint32_t a;
    asm("{ .reg .u64 t; cvta.to.shared.u64 t, %1; cvt.u32.u64 %0, t; }" : "=r"(a) : "l"(p));
    return a;
}
__device__ __forceinline__ void mma_f16(float* d, const unsigned* a, const unsigned* b) {
    asm volatile("mma.sync.aligned.m16n8k16.row.col.f32.f16.f16.f32 "
                 "{%0,%1,%2,%3},{%4,%5,%6,%7},{%8,%9},{%0,%1,%2,%3};"
                 : "+f"(d[0]), "+f"(d[1]), "+f"(d[2]), "+f"(d[3])
                 : "r"(a[0]), "r"(a[1]), "r"(a[2]), "r"(a[3]), "r"(b[0]), "r"(b[1]));
}
__device__ __forceinline__ void cp16(uint32_t saddr, const void* g) {
    asm volatile("cp.async.ca.shared.global [%0], [%1], 16;" :: "r"(saddr), "l"(g));
}

/* ---------------- weight fp16 conversion ---------------- */
__global__ void wconv_h_kernel(const float* __restrict__ in, __half* __restrict__ out, int n) {
    int idx = blockIdx.x * 256 + threadIdx.x;
    if (idx < n) out[idx] = __float2half(in[idx]);
}
__global__ void wconv_qkv_h_kernel(const float* __restrict__ in, __half* __restrict__ out,
                                   int part) {
    int idx = blockIdx.x * 256 + threadIdx.x;
    int lay = idx / 589824, w = idx % 589824;
    out[(size_t)lay * 1769472 + (size_t)part * 589824 + w] = __float2half(in[idx]);
}
__global__ void bpack_kernel(const float* __restrict__ bq, const float* __restrict__ bk,
                             const float* __restrict__ bv, float* __restrict__ out) {
    int idx = blockIdx.x * 256 + threadIdx.x;
    if (idx >= NLAYER * QKVS) return;
    int lay = idx / QKVS, c = idx % QKVS;
    float v;
    if (c < 768) v = bq[lay * 768 + c];
    else if (c < 1536) v = bk[lay * 768 + c - 768];
    else v = bv[lay * 768 + c - 1536];
    out[idx] = v;
}

/* =========== cp.async 4-stage fp16 mma GEMM =========== */
#define STAGES 4
#define HSTG   10240
#define GSMH   (STAGES * HSTG * 2)         /* 81920 bytes */

template<int RELU, int RES, int OUTH>
__global__ __launch_bounds__(128, 2) void hgemm(const __half* __restrict__ A,
                                                const __half* __restrict__ W,
                                                const float* __restrict__ bias,
                                                const float* __restrict__ Rsrc,
                                                void* __restrict__ Cv,
                                                int M, int N, int K) {
    extern __shared__ __half hsm[];
    const int t = threadIdx.x;
    const int wid = t >> 5, lane = t & 31;
    const int wm = wid >> 1, wn = wid & 1;
    const int m0 = blockIdx.y * 128, n0 = blockIdx.x * 128;
    const int fr = lane >> 2, fc = lane & 3;

    const __half* Agp = A + (size_t)m0 * K;
    const __half* Bgp = W + (size_t)n0 * K;

    float acc[4][8][4];
#pragma unroll
    for (int i = 0; i < 4; ++i)
#pragma unroll
        for (int j = 0; j < 8; ++j)
#pragma unroll
            for (int r = 0; r < 4; ++r) acc[i][j][r] = 0.f;

    const int NT = K >> 5;

#pragma unroll
    for (int s = 0; s < STAGES - 1; ++s) {
        __half* st = hsm + s * HSTG;
        const __half* Ag = Agp + s * 32;
        const __half* Bg = Bgp + s * 32;
#pragma unroll
        for (int j = 0; j < 4; ++j) {
            int id = t + j * 128;
            int row = id >> 2, c8 = (id & 3) * 8;
            cp16(s2u(st + row * 40 + c8), Ag + (size_t)row * K + c8);
            cp16(s2u(st + 5120 + row * 40 + c8), Bg + (size_t)row * K + c8);
        }
        asm volatile("cp.async.commit_group;");
    }

    for (int kb = 0; kb < NT; ++kb) {
        asm volatile("cp.async.wait_group %0;" :: "n"(STAGES - 2));
        __syncthreads();
        if (kb + STAGES - 1 < NT) {
            __half* st = hsm + ((kb + STAGES - 1) & (STAGES - 1)) * HSTG;
            const __half* Ag = Agp + (kb + STAGES - 1) * 32;
            const __half* Bg = Bgp + (kb + STAGES - 1) * 32;
#pragma unroll
            for (int j = 0; j < 4; ++j) {
                int id = t + j * 128;
                int row = id >> 2, c8 = (id & 3) * 8;
                cp16(s2u(st + row * 40 + c8), Ag + (size_t)row * K + c8);
                cp16(s2u(st + 5120 + row * 40 + c8), Bg + (size_t)row * K + c8);
            }
        }
        asm volatile("cp.async.commit_group;");

        const __half* Ab = hsm + (kb & (STAGES - 1)) * HSTG;
        const __half* Bb = Ab + 5120;
#pragma unroll
        for (int ks = 0; ks < 2; ++ks) {
            const int k0 = ks * 16;
            unsigned af[4][4], bf[8][2];
#pragma unroll
            for (int mt = 0; mt < 4; ++mt) {
                int row = wm * 64 + mt * 16 + fr;
                af[mt][0] = *(const uint32_t*)&Ab[row * 40 + k0 + 2 * fc];
                af[mt][1] = *(const uint32_t*)&Ab[(row + 8) * 40 + k0 + 2 * fc];
                af[mt][2] = *(const uint32_t*)&Ab[row * 40 + k0 + 2 * fc + 8];
                af[mt][3] = *(const uint32_t*)&Ab[(row + 8) * 40 + k0 + 2 * fc + 8];
            }
#pragma unroll
            for (int nt = 0; nt < 8; ++nt) {
                int col = wn * 64 + nt * 8 + fr;
                bf[nt][0] = *(const uint32_t*)&Bb[col * 40 + k0 + 2 * fc];
                bf[nt][1] = *(const uint32_t*)&Bb[col * 40 + k0 + 2 * fc + 8];
            }
#pragma unroll
            for (int mt = 0; mt < 4; ++mt)
#pragma unroll
                for (int nt = 0; nt < 8; ++nt)
                    mma_f16(acc[mt][nt], af[mt], bf[nt]);
        }
    }

    const int c2 = (lane & 3) * 2;
#pragma unroll
    for (int mt = 0; mt < 4; ++mt) {
        int row = m0 + wm * 64 + mt * 16 + fr;
#pragma unroll
        for (int nt = 0; nt < 8; ++nt) {
            int col = n0 + wn * 64 + nt * 8 + c2;
            size_t i0 = (size_t)row * N + col;
            size_t i1 = (size_t)(row + 8) * N + col;
            float b0 = bias[col], b1 = bias[col + 1];
            float v0 = acc[mt][nt][0] + b0, v1 = acc[mt][nt][1] + b1;
            float v2 = acc[mt][nt][2] + b0, v3 = acc[mt][nt][3] + b1;
            if (RES) {
                float2 r0 = *(const float2*)&Rsrc[i0];
                float2 r1 = *(const float2*)&Rsrc[i1];
                v0 += r0.x; v1 += r0.y; v2 += r1.x; v3 += r1.y;
            }
            if (RELU) { v0 = fmaxf(v0, 0.f); v1 = fmaxf(v1, 0.f); v2 = fmaxf(v2, 0.f); v3 = fmaxf(v3, 0.f); }
            if (OUTH) {
                __half* Ch = (__half*)Cv;
                *(__half2*)(Ch + i0) = __floats2half2_rn(v0, v1);
                *(__half2*)(Ch + i1) = __floats2half2_rn(v2, v3);
            } else {
                float* Cf = (float*)Cv;
                float2 o0 = {v0, v1}, o1 = {v2, v3};
                *(float2*)&Cf[i0] = o0;
                *(float2*)&Cf[i1] = o1;
            }
        }
    }
}

/* ---------------- RevIN stats ---------------- */
__global__ void revin_stats_kernel(const float* __restrict__ x, float* __restrict__ mean,
                                   float* __restrict__ stdv) {
    int bm = blockIdx.x;
    int b = bm / MM, m = bm % MM;
    const float* xp = x + (size_t)b * LL * MM + m;
    float s = 0.f, s2 = 0.f;
    for (int l = threadIdx.x; l < LL; l += 256) {
        float v = xp[(size_t)l * MM];
        s += v; s2 += v * v;
    }
    __shared__ float sh0[256], sh1[256];
    sh0[threadIdx.x] = s; sh1[threadIdx.x] = s2;
    __syncthreads();
    for (int off = 128; off > 0; off >>= 1) {
        if (threadIdx.x < off) { sh0[threadIdx.x] += sh0[threadIdx.x + off]; sh1[threadIdx.x] += sh1[threadIdx.x + off]; }
        __syncthreads();
    }
    if (threadIdx.x == 0) {
        float mu = sh0[0] * (1.f / LL);
        float var = sh1[0] * (1.f / LL) - mu * mu;
        mean[bm] = mu;
        stdv[bm] = sqrtf(var + EPSF);
    }
}

/* ---------------- patches ---------------- */
__global__ void patches_kernel(const float* __restrict__ x, const float* __restrict__ mean,
                               const float* __restrict__ stdv, const float* __restrict__ rw,
                               const float* __restrict__ rb, float* __restrict__ patches) {
    int idx = blockIdx.x * 256 + threadIdx.x;
    int p = idx & 15;
    int n = (idx >> 4) & 63;
    int bm = idx >> 10;
    int m = bm % MM;
    int b = bm / MM;
    int l = n * 16 + p;
    float v = x[(size_t)b * LL * MM + (size_t)l * MM + m];
    v = (v - mean[bm]) / stdv[bm] * rw[m] + rb[m];
    patches[idx] = v;
}

/* ---------------- composed spectral transform ---------------- */
__global__ void computeT_kernel(const float* __restrict__ wr, const float* __restrict__ wi,
                                float* __restrict__ T) {
    int lay = blockIdx.x;
    __shared__ float Ur[32][64], Ui[32][64];
    const float* wrp = wr + (size_t)lay * FREQ * A2;
    const float* wip = wi + (size_t)lay * FREQ * A2;
    const float c0 = 6.28318530717958647692f / 64.f;
    for (int e = threadIdx.x; e < 32 * 64; e += 256) {
        int d = e >> 6, n = e & 63;
        float sr = 0.f, si = 0.f;
        for (int kf = 0; kf < FREQ; ++kf) {
            float ang = c0 * (float)(kf * n);
            float cv, sv;
            sincosf(ang, &sv, &cv);
            sr += wrp[kf * A2 + d] * cv;
            si += wip[kf * A2 + d] * (-sv);
        }
        Ur[d][n] = sr; Ui[d][n] = si;
    }
    __syncthreads();
    for (int e = threadIdx.x; e < 64 * 64; e += 256) {
        int a = e >> 6, n = e & 63;
        float tval = Ur[0][n];
        for (int d = 1; d < 32; ++d) {
            float ang = c0 * (float)(d * a);
            float cv, sv;
            sincosf(ang, &sv, &cv);
            tval += 2.f * (Ur[d][n] * cv - Ui[d][n] * sv);
        }
        T[lay * 4096 + e] = tval * (1.f / 64.f);
    }
}

/* ---------------- instance-norm stats ---------------- */
__global__ void pn_stats_kernel(const float* __restrict__ patches, float* __restrict__ mu,
                                float* __restrict__ rv) {
    int idx = blockIdx.x * 256 + threadIdx.x;
    int b = idx >> 10;
    int np = idx & 1023;
    const float* pp = patches + (size_t)b * 21504 + np;
    float s = 0.f, s2 = 0.f;
#pragma unroll
    for (int m = 0; m < MM; ++m) { float v = pp[m * 1024]; s += v; s2 += v * v; }
    float m0 = s * (1.f / MM);
    float var = s2 * (1.f / MM) - m0 * m0;
    mu[idx] = m0;
    rv[idx] = rsqrtf(var + EPSF);
}

/* ---------------- spectral mixing ---------------- */
__global__ void spect_kernel(const float* __restrict__ patches, const float* __restrict__ mu,
                             const float* __restrict__ rv, const float* __restrict__ g,
                             const float* __restrict__ be, const float* __restrict__ T,
                             float* __restrict__ ad) {
    int idx = blockIdx.x * 256 + threadIdx.x;
    int p = idx & 15;
    int a = (idx >> 4) & 63;
    int bm = idx >> 10;
    int m = bm % MM;
    int b = bm / MM;
    float gm = g[m], bm_ = be[m];
    const float* pp  = patches + (size_t)bm * 1024 + p;
    const float* mup = mu + b * 1024 + p;
    const float* rvp = rv + b * 1024 + p;
    const float* Tp  = T + a * 64;
    float acc = 0.f;
#pragma unroll 8
    for (int n = 0; n < 64; ++n) {
        float pn = (pp[n * 16] - mup[n * 16]) * rvp[n * 16] * gm + bm_;
        acc += Tp[n] * pn;
    }
    ad[idx] = acc;
}

/* ---------------- embeddings ---------------- */
template<int ADD>
__global__ __launch_bounds__(256) void embed_kernel(const float* __restrict__ src,
                                                    const float* __restrict__ Hin,
                                                    const float* __restrict__ inw,
                                                    const float* __restrict__ inb,
                                                    float* __restrict__ out32,
                                                    __half* __restrict__ out16) {
    __shared__ float ps[1024];
    int blk = blockIdx.x;
    int t = threadIdx.x;
    const float4* sp = (const float4*)(src + (size_t)blk * 1024);
    ((float4*)ps)[t] = sp[t];
    float w[3][16], bb[3];
#pragma unroll
    for (int j = 0; j < 3; ++j) {
        int c = t + 256 * j;
        bb[j] = inb[c];
#pragma unroll
        for (int p4 = 0; p4 < 4; ++p4) {
            float4 wv = *(const float4*)(inw + (size_t)c * 16 + p4 * 4);
            w[j][p4 * 4] = wv.x; w[j][p4 * 4 + 1] = wv.y; w[j][p4 * 4 + 2] = wv.z; w[j][p4 * 4 + 3] = wv.w;
        }
    }
    __syncthreads();
    size_t rowbase = (size_t)blk * 64 * DD;
    for (int r = 0; r < 64; ++r) {
        float pr[16];
#pragma unroll
        for (int p4 = 0; p4 < 4; ++p4) {
            float4 pv = *(const float4*)&ps[r * 16 + p4 * 4];
            pr[p4 * 4] = pv.x; pr[p4 * 4 + 1] = pv.y; pr[p4 * 4 + 2] = pv.z; pr[p4 * 4 + 3] = pv.w;
        }
        size_t ro = rowbase + (size_t)r * DD;
#pragma unroll
        for (int j = 0; j < 3; ++j) {
            float acc = bb[j];
            if (ADD) acc += Hin[ro + t + 256 * j];
#pragma unroll
            for (int p = 0; p < 16; ++p) acc = fmaf(pr[p], w[j][p], acc);
            out32[ro + t + 256 * j] = acc;
            if (ADD) out16[ro + t + 256 * j] = __float2half(acc);
        }
    }
}

/* ---------------- attention: fused scores + bias + softmax (half qkv) --------- */
__global__ __launch_bounds__(256) void scores_softmax_kernel(const __half* __restrict__ qkv,
                                                             const float* __restrict__ bias,
                                                             float* __restrict__ sc) {
    int bm = blockIdx.x, h = blockIdx.y;
    __shared__ float qs[64 * 96];
    __shared__ float ksT[96 * 68];
    int t = threadIdx.x;
    const __half* qg = qkv + (size_t)bm * 64 * QKVS + h * EE;
    const __half* kg = qkv + (size_t)bm * 64 * QKVS + 768 + h * EE;
    for (int i = t; i < 768; i += 256) {
        int r = i / 12, c = i % 12;
        uint4 raw = *(const uint4*)(qg + (size_t)r * QKVS + c * 8);
        const __half2* hp = (const __half2*)&raw;
        float* dst = &qs[r * 96 + c * 8];
        float2 f0 = __half22float2(hp[0]), f1 = __half22float2(hp[1]);
        float2 f2 = __half22float2(hp[2]), f3 = __half22float2(hp[3]);
        dst[0] = f0.x; dst[1] = f0.y; dst[2] = f1.x; dst[3] = f1.y;
        dst[4] = f2.x; dst[5] = f2.y; dst[6] = f3.x; dst[7] = f3.y;
    }
    for (int i = t; i < 768; i += 256) {
        int s = i / 12, c = i % 12;
        uint4 raw = *(const uint4*)(kg + (size_t)s * QKVS + c * 8);
        const __half2* hp = (const __half2*)&raw;
        float2 f0 = __half22float2(hp[0]), f1 = __half22float2(hp[1]);
        float2 f2 = __half22float2(hp[2]), f3 = __half22float2(hp[3]);
        ksT[(c * 8 + 0) * 68 + s] = f0.x; ksT[(c * 8 + 1) * 68 + s] = f0.y;
        ksT[(c * 8 + 2) * 68 + s] = f1.x; ksT[(c * 8 + 3) * 68 + s] = f1.y;
        ksT[(c * 8 + 4) * 68 + s] = f2.x; ksT[(c * 8 + 5) * 68 + s] = f2.y;
        ksT[(c * 8 + 6) * 68 + s] = f3.x; ksT[(c * 8 + 7) * 68 + s] = f3.y;
    }
    __syncthreads();
    int l0 = (t >> 4) * 4, s0 = (t & 15) * 4;
    float acc[4][4] = {};
    for (int e = 0; e < 96; ++e) {
        float4 kv = *(const float4*)&ksT[e * 68 + s0];
#pragma unroll
        for (int i2 = 0; i2 < 4; ++i2) {
            float qv = qs[(l0 + i2) * 96 + e];
            acc[i2][0] = fmaf(qv, kv.x, acc[i2][0]);
            acc[i2][1] = fmaf(qv, kv.y, acc[i2][1]);
            acc[i2][2] = fmaf(qv, kv.z, acc[i2][2]);
            acc[i2][3] = fmaf(qv, kv.w, acc[i2][3]);
        }
    }
    const float SCALE = 0.10206207261596575f;
    float* scp = sc + (size_t)(bm * 8 + h) * 4096;
#pragma unroll
    for (int i2 = 0; i2 < 4; ++i2) {
        int l = l0 + i2;
        float v[4];
#pragma unroll
        for (int j = 0; j < 4; ++j)
            v[j] = acc[i2][j] * SCALE + bias[(l * 64 + s0 + j) * 8 + h];
        float mx = fmaxf(fmaxf(v[0], v[1]), fmaxf(v[2], v[3]));
#pragma unroll
        for (int off = 8; off > 0; off >>= 1)
            mx = fmaxf(mx, __shfl_xor_sync(0xffffffffu, mx, off, 16));
        float sum = 0.f;
#pragma unroll
        for (int j = 0; j < 4; ++j) { v[j] = expf(v[j] - mx); sum += v[j]; }
#pragma unroll
        for (int off = 8; off > 0; off >>= 1)
            sum += __shfl_xor_sync(0xffffffffu, sum, off, 16);
        float inv = 1.f / sum;
        float4 o4 = {v[0] * inv, v[1] * inv, v[2] * inv, v[3] * inv};
        *(float4*)&scp[l * 64 + s0] = o4;
    }
}

/* ---------------- attention: tiled AV (half qkv in, half out) ---------------- */
__global__ __launch_bounds__(256) void av_tile_kernel(const float* __restrict__ sc,
                                                      const __half* __restrict__ qkv,
                                                      __half* __restrict__ o) {
    int bm = blockIdx.x, h = blockIdx.y;
    __shared__ float at[64 * 65];
    __shared__ float vs[64 * 96];
    int t = threadIdx.x;
    const float* ap = sc + (size_t)(bm * 8 + h) * 4096;
    const __half* vg = qkv + (size_t)bm * 64 * QKVS + 1536 + h * EE;
    for (int i = t; i < 1024; i += 256) {
        int l = i >> 4, c = i & 15;
        float4 a4 = *(const float4*)(ap + l * 64 + c * 4);
        at[l * 65 + c * 4 + 0] = a4.x; at[l * 65 + c * 4 + 1] = a4.y;
        at[l * 65 + c * 4 + 2] = a4.z; at[l * 65 + c * 4 + 3] = a4.w;
    }
    for (int i = t; i < 768; i += 256) {
        int s = i / 12, c = i % 12;
        uint4 raw = *(const uint4*)(vg + (size_t)s * QKVS + c * 8);
        const __half2* hp = (const __half2*)&raw;
        float* dst = &vs[s * 96 + c * 8];
        float2 f0 = __half22float2(hp[0]), f1 = __half22float2(hp[1]);
        float2 f2 = __half22float2(hp[2]), f3 = __half22float2(hp[3]);
        dst[0] = f0.x; dst[1] = f0.y; dst[2] = f1.x; dst[3] = f1.y;
        dst[4] = f2.x; dst[5] = f2.y; dst[6] = f3.x; dst[7] = f3.y;
    }
    __syncthreads();
    int l0 = (t >> 4) * 4, e0 = (t & 15) * 6;
    float acc[4][6] = {};
    for (int s = 0; s < 64; ++s) {
        float av_[4], vv[6];
#pragma unroll
        for (int i2 = 0; i2 < 4; ++i2) av_[i2] = at[(l0 + i2) * 65 + s];
#pragma unroll
        for (int j = 0; j < 6; ++j) vv[j] = vs[s * 96 + e0 + j];
#pragma unroll
        for (int i2 = 0; i2 < 4; ++i2)
#pragma unroll
            for (int j = 0; j < 6; ++j) acc[i2][j] = fmaf(av_[i2], vv[j], acc[i2][j]);
    }
    __half* op = o + (size_t)bm * 64 * DD + h * EE;
#pragma unroll
    for (int i2 = 0; i2 < 4; ++i2)
#pragma unroll
        for (int j = 0; j < 6; ++j)
            op[(size_t)(l0 + i2) * DD + e0 + j] = __float2half(acc[i2][j]);
}

/* ---------------- batchnorm ---------------- */
__global__ void zero_kernel(float* __restrict__ p, int n) {
    int idx = blockIdx.x * 256 + threadIdx.x;
    if (idx < n) p[idx] = 0.f;
}

__global__ void bn_reduce_kernel(const float* __restrict__ X, float* __restrict__ sum,
                                 float* __restrict__ sq) {
    int r0 = blockIdx.x * 128;
    float s[3] = {0.f, 0.f, 0.f}, q[3] = {0.f, 0.f, 0.f};
    for (int r = 0; r < 128; ++r) {
        const float* xp = X + (size_t)(r0 + r) * DD;
#pragma unroll
        for (int j = 0; j < 3; ++j) {
            float v = xp[threadIdx.x + j * 256];
            s[j] += v; q[j] += v * v;
        }
    }
#pragma unroll
    for (int j = 0; j < 3; ++j) {
        atomicAdd(&sum[threadIdx.x + j * 256], s[j]);
        atomicAdd(&sq[threadIdx.x + j * 256], q[j]);
    }
}

template<int WH>
__global__ void bn_apply_kernel(float* __restrict__ X, const float* __restrict__ sum,
                                const float* __restrict__ sq, const float* __restrict__ g,
                                const float* __restrict__ be, __half* __restrict__ Xh) {
    int idx = blockIdx.x * 256 + threadIdx.x;
    int c = idx % DD;
    const float inv_n = 1.f / (float)ROWS;
    float mean = sum[c] * inv_n;
    float var = sq[c] * inv_n - mean * mean;
    float v = (X[idx] - mean) * rsqrtf(var + EPSF) * g[c] + be[c];
    X[idx] = v;
    if (WH) Xh[idx] = __float2half(v);
}

/* fused bn2 + final norm (layer 3): bn3(bn2(X)) from X's stats */
__global__ void bn_apply_final_kernel(float* __restrict__ X, const float* __restrict__ sum,
                                      const float* __restrict__ sq,
                                      const float* __restrict__ g2, const float* __restrict__ b2,
                                      const float* __restrict__ g3, const float* __restrict__ b3) {
    int idx = blockIdx.x * 256 + threadIdx.x;
    int c = idx % DD;
    const float inv_n = 1.f / (float)ROWS;
    float mean = sum[c] * inv_n;
    float var = sq[c] * inv_n - mean * mean;
    float r = rsqrtf(var + EPSF);
    float s = g2[c] * r;
    float xv = (X[idx] - mean) * s;                 /* = bn2(X) - b2 */
    float r2 = rsqrtf(s * s * var + EPSF);
    X[idx] = xv * r2 * g3[c] + b3[c];
}

/* ---------------- final projection ---------------- */
__global__ void final_gemm_kernel(const float* __restrict__ hbuf, const float* __restrict__ ow,
                                  float* __restrict__ osmall) {
    __shared__ float hs[8 * 1024];
    int row0 = blockIdx.x * 8;
    int k0 = blockIdx.y * 1024;
    for (int j = threadIdx.x; j < 2048; j += 128) {
        int r = j >> 8, kq = j & 255;
        *(float4*)&hs[r * 1024 + kq * 4] =
            *(const float4*)&hbuf[(size_t)(row0 + r) * 49152 + k0 + kq * 4];
    }
    __syncthreads();
    int p = threadIdx.x;
    if (p < PREDN) {
        float acc[8] = {0.f, 0.f, 0.f, 0.f, 0.f, 0.f, 0.f, 0.f};
        const float* wp = ow + (size_t)p * 49152 + k0;
        for (int kq = 0; kq < 256; ++kq) {
            float4 w4 = *(const float4*)(wp + kq * 4);
#pragma unroll
            for (int r = 0; r < 8; ++r) {
                const float* hr = &hs[r * 1024 + kq * 4];
                acc[r] += hr[0] * w4.x + hr[1] * w4.y + hr[2] * w4.z + hr[3] * w4.w;
            }
        }
#pragma unroll
        for (int r = 0; r < 8; ++r) atomicAdd(&osmall[(row0 + r) * PREDN + p], acc[r]);
    }
}

/* ---------------- de-norm ---------------- */
__global__ void denorm_kernel(const float* __restrict__ osmall, const float* __restrict__ outb,
                              const float* __restrict__ rw, const float* __restrict__ rb,
                              const float* __restrict__ mean, const float* __restrict__ stdv,
                              float* __restrict__ out) {
    int idx = blockIdx.x * 256 + threadIdx.x;
    int m = idx % MM;
    int pr = (idx / MM) % PREDN;
    int b = idx / (MM * PREDN);
    int bm = b * MM + m;
    float v = osmall[bm * PREDN + pr] + outb[pr];
    v = (v - rb[m]) / (rw[m] + 1e-10f);
    out[idx] = v * stdv[bm] + mean[bm];
}

/* ---------------- launcher ---------------- */
extern "C" void kernel_launch(void* const* d_in, const int* in_sizes, int n_in,
                              void* d_out, int out_size) {
    const float* x         = (const float*)d_in[0];
    const float* attn_bias = (const float*)d_in[1];
    const float* revin_w   = (const float*)d_in[2];
    const float* revin_b   = (const float*)d_in[3];
    const float* in_w      = (const float*)d_in[4];
    const float* in_b      = (const float*)d_in[5];
    const float* ln1_g     = (const float*)d_in[6];
    const float* ln1_b     = (const float*)d_in[7];
    const float* spect_wr  = (const float*)d_in[8];
    const float* spect_wi  = (const float*)d_in[9];
    const float* Wq        = (const float*)d_in[10];
    const float* bq        = (const float*)d_in[11];
    const float* Wk        = (const float*)d_in[12];
    const float* bk        = (const float*)d_in[13];
    const float* Wv        = (const float*)d_in[14];
    const float* bv        = (const float*)d_in[15];
    const float* Wo        = (const float*)d_in[16];
    const float* bo        = (const float*)d_in[17];
    const float* c1_w      = (const float*)d_in[18];
    const float* c1_b      = (const float*)d_in[19];
    const float* c2_w      = (const float*)d_in[20];
    const float* c2_b      = (const float*)d_in[21];
    const float* bn1_g     = (const float*)d_in[22];
    const float* bn1_b     = (const float*)d_in[23];
    const float* bn2_g     = (const float*)d_in[24];
    const float* bn2_b     = (const float*)d_in[25];
    const float* norm_g    = (const float*)d_in[26];
    const float* norm_b    = (const float*)d_in[27];
    const float* out_w     = (const float*)d_in[28];
    const float* out_b     = (const float*)d_in[29];

    float* base = nullptr;
    cudaGetSymbolAddress((void**)&base, g_buf);
    float* mean   = base + OFF_MEAN;
    float* stdv   = base + OFF_STD;
    float* patch  = base + OFF_PATCH;
    float* Tm     = base + OFF_T;
    float* mu     = base + OFF_MU;
    float* rv     = base + OFF_RV;
    float* ad     = base + OFF_AD;
    float* bnsum  = base + OFF_BNSUM;
    float* bnsq   = base + OFF_BNSQ;
    float* osmall = base + OFF_OSMALL;
    float* h      = base + OFF_H;
    float* y      = base + OFF_Y;
    __half* qkvh  = (__half*)(base + OFF_QKVH);
    float* sc     = base + OFF_SC;
    __half* y16   = (__half*)(base + OFF_Y16);
    __half* o16   = (__half*)(base + OFF_O16);
    __half* f4h   = (__half*)(base + OFF_F4H);
    __half* wh    = (__half*)(base + OFF_WH);
    __half* WHqkv = wh;
    __half* WHo   = wh + 5308416u;
    __half* WH1   = wh + 7077888u;
    __half* WH2   = wh + 14155776u;
    float* bqkv   = base + OFF_BQKV;

    cudaFuncSetAttribute(hgemm<0, 0, 1>, cudaFuncAttributeMaxDynamicSharedMemorySize, GSMH);
    cudaFuncSetAttribute(hgemm<0, 1, 0>, cudaFuncAttributeMaxDynamicSharedMemorySize, GSMH);
    cudaFuncSetAttribute(hgemm<1, 0, 1>, cudaFuncAttributeMaxDynamicSharedMemorySize, GSMH);

    const int TPB = 256;
    const int G_ED = (ROWS * DD) / TPB;

    wconv_qkv_h_kernel<<<1769472 / TPB, TPB>>>(Wq, WHqkv, 0);
    wconv_qkv_h_kernel<<<1769472 / TPB, TPB>>>(Wk, WHqkv, 1);
    wconv_qkv_h_kernel<<<1769472 / TPB, TPB>>>(Wv, WHqkv, 2);
    wconv_h_kernel<<<1769472 / TPB, TPB>>>(Wo, WHo, 1769472);
    wconv_h_kernel<<<7077888 / TPB, TPB>>>(c1_w, WH1, 7077888);
    wconv_h_kernel<<<7077888 / TPB, TPB>>>(c2_w, WH2, 7077888);
    bpack_kernel<<<27, TPB>>>(bq, bk, bv, bqkv);

    revin_stats_kernel<<<BMC, TPB>>>(x, mean, stdv);
    patches_kernel<<<344064 / TPB, TPB>>>(x, mean, stdv, revin_w, revin_b, patch);
    computeT_kernel<<<NLAYER, TPB>>>(spect_wr, spect_wi, Tm);
    embed_kernel<0><<<BMC, TPB>>>(patch, nullptr, in_w, in_b, h, nullptr);

    dim3 gQKV(QKVS / 128, ROWS / 128);
    dim3 gP(DD / 128, ROWS / 128);
    dim3 gF1(FF4 / 128, ROWS / 128);
    dim3 gS(BMC, HH);
    dim3 gAV(BMC, HH);

    for (int i = 0; i < NLAYER; ++i) {
        pn_stats_kernel<<<16384 / TPB, TPB>>>(patch, mu, rv);
        spect_kernel<<<344064 / TPB, TPB>>>(patch, mu, rv, ln1_g + i * MM, ln1_b + i * MM,
                                            Tm + i * 4096, ad);
        embed_kernel<1><<<BMC, TPB>>>(ad, h, in_w, in_b, y, y16);

        hgemm<0, 0, 1><<<gQKV, 128, GSMH>>>(y16, WHqkv + (size_t)i * 1769472u,
                                            bqkv + i * QKVS, nullptr, qkvh, ROWS, QKVS, DD);

        scores_softmax_kernel<<<gS, TPB>>>(qkvh, attn_bias, sc);
        av_tile_kernel<<<gAV, TPB>>>(sc, qkvh, o16);

        hgemm<0, 1, 0><<<gP, 128, GSMH>>>(o16, WHo + (size_t)i * DD * DD, bo + i * DD,
                                          y, y, ROWS, DD, DD);

        zero_kernel<<<6, TPB>>>(bnsum, 1536);
        bn_reduce_kernel<<<ROWS / 128, TPB>>>(y, bnsum, bnsq);
        bn_apply_kernel<1><<<G_ED, TPB>>>(y, bnsum, bnsq, bn1_g + i * DD, bn1_b + i * DD, y16);

        hgemm<1, 0, 1><<<gF1, 128, GSMH>>>(y16, WH1 + (size_t)i * FF4 * DD, c1_b + i * FF4,
                                           nullptr, f4h, ROWS, FF4, DD);
        hgemm<0, 1, 0><<<gP, 128, GSMH>>>(f4h, WH2 + (size_t)i * DD * FF4, c2_b + i * DD,
                                          y, h, ROWS, DD, FF4);

        zero_kernel<<<6, TPB>>>(bnsum, 1536);
        bn_reduce_kernel<<<ROWS / 128, TPB>>>(h, bnsum, bnsq);
        if (i < NLAYER - 1) {
            bn_apply_kernel<0><<<G_ED, TPB>>>(h, bnsum, bnsq, bn2_g + i * DD, bn2_b + i * DD, nullptr);
        } else {
            bn_apply_final_kernel<<<G_ED, TPB>>>(h, bnsum, bnsq, bn2_g + i * DD, bn2_b + i * DD,
                                                 norm_g, norm_b);
        }
    }

    zero_kernel<<<32256 / TPB, TPB>>>(osmall, 32256);
    final_gemm_kernel<<<dim3(BMC / 8, 48), 128>>>(h, out_w, osmall);
    denorm_kernel<<<32256 / TPB, TPB>>>(osmall, out_b, revin_w, revin_b, mean, stdv,
                                        (float*)d_out);
}

// round 11
// speedup vs baseline: 1.1306x; 1.0859x over previous
#include <cuda_runtime.h>
#include <cuda_fp16.h>
#include <math.h>
#include <stdint.h>

#define BB 16
#define LL 1024
#define MM 21
#define PP 16
#define NN 64
#define DD 768
#define HH 8
#define EE 96
#define FF4 3072
#define NLAYER 3
#define FREQ 33
#define A2 32
#define PREDN 96
#define BMC (BB*MM)          /* 336 */
#define ROWS (BMC*NN)        /* 21504 */
#define EPSF 1e-5f
#define QKVS 2304

/* ---------------- scratch layout (float units) ---------------- */
#define OFF_MEAN   0u
#define OFF_STD    512u
#define OFF_PATCH  1024u
#define OFF_T      345088u
#define OFF_MU     357376u
#define OFF_RV     373760u
#define OFF_AD     390144u
#define OFF_BNSUM  734208u
#define OFF_BNSQ   734976u
#define OFF_OSMALL 735744u
#define OFF_H      768000u
#define OFF_Y      (OFF_H + 16515072u)
#define OFF_QKVH   (OFF_Y + 16515072u)          /* ROWS*2304 halfs */
#define OFF_SC     (OFF_QKVH + 24772608u)
#define OFF_Y16    (OFF_SC + 11010048u)
#define OFF_O16    (OFF_Y16 + 8257536u)
#define OFF_F4H    (OFF_O16 + 8257536u)
#define OFF_WH     (OFF_F4H + 33030144u)
#define OFF_BQKV   (OFF_WH + 10616832u)
#define TOTAL_F    (OFF_BQKV + 8192u)

__device__ float g_buf[TOTAL_F];

/* ================= helpers ================= */
__device__ __forceinline__ uint32_t s2u(const void* p) {
    uint32_t a;
    asm("{ .reg .u64 t; cvta.to.shared.u64 t, %1; cvt.u32.u64 %0, t; }" : "=r"(a) : "l"(p));
    return a;
}
__device__ __forceinline__ void mma_f16(float* d, const unsigned* a, const unsigned* b) {
    asm volatile("mma.sync.aligned.m16n8k16.row.col.f32.f16.f16.f32 "
                 "{%0,%1,%2,%3},{%4,%5,%6,%7},{%8,%9},{%0,%1,%2,%3};"
                 : "+f"(d[0]), "+f"(d[1]), "+f"(d[2]), "+f"(d[3])
                 : "r"(a[0]), "r"(a[1]), "r"(a[2]), "r"(a[3]), "r"(b[0]), "r"(b[1]));
}
__device__ __forceinline__ void cp16(uint32_t saddr, const void* g) {
    asm volatile("cp.async.ca.shared.global [%0], [%1], 16;" :: "r"(saddr), "l"(g));
}

/* ---------------- weight fp16 conversion ---------------- */
__global__ void wconv_h_kernel(const float* __restrict__ in, __half* __restrict__ out, int n) {
    int idx = blockIdx.x * 256 + threadIdx.x;
    if (idx < n) out[idx] = __float2half(in[idx]);
}
__global__ void wconv_qkv_h_kernel(const float* __restrict__ in, __half* __restrict__ out,
                                   int part) {
    int idx = blockIdx.x * 256 + threadIdx.x;
    int lay = idx / 589824, w = idx % 589824;
    out[(size_t)lay * 1769472 + (size_t)part * 589824 + w] = __float2half(in[idx]);
}
__global__ void bpack_kernel(const float* __restrict__ bq, const float* __restrict__ bk,
                             const float* __restrict__ bv, float* __restrict__ out) {
    int idx = blockIdx.x * 256 + threadIdx.x;
    if (idx >= NLAYER * QKVS) return;
    int lay = idx / QKVS, c = idx % QKVS;
    float v;
    if (c < 768) v = bq[lay * 768 + c];
    else if (c < 1536) v = bk[lay * 768 + c - 768];
    else v = bv[lay * 768 + c - 1536];
    out[idx] = v;
}

/* =========== cp.async 4-stage fp16 mma GEMM =========== */
#define STAGES 4
#define HSTG   10240
#define GSMH   (STAGES * HSTG * 2)         /* 81920 bytes */

template<int RELU, int RES, int OUTH>
__global__ __launch_bounds__(128, 2) void hgemm(const __half* __restrict__ A,
                                                const __half* __restrict__ W,
                                                const float* __restrict__ bias,
                                                const float* __restrict__ Rsrc,
                                                void* __restrict__ Cv,
                                                int M, int N, int K) {
    extern __shared__ __half hsm[];
    const int t = threadIdx.x;
    const int wid = t >> 5, lane = t & 31;
    const int wm = wid >> 1, wn = wid & 1;
    const int m0 = blockIdx.y * 128, n0 = blockIdx.x * 128;
    const int fr = lane >> 2, fc = lane & 3;

    const __half* Agp = A + (size_t)m0 * K;
    const __half* Bgp = W + (size_t)n0 * K;

    float acc[4][8][4];
#pragma unroll
    for (int i = 0; i < 4; ++i)
#pragma unroll
        for (int j = 0; j < 8; ++j)
#pragma unroll
            for (int r = 0; r < 4; ++r) acc[i][j][r] = 0.f;

    const int NT = K >> 5;

#pragma unroll
    for (int s = 0; s < STAGES - 1; ++s) {
        __half* st = hsm + s * HSTG;
        const __half* Ag = Agp + s * 32;
        const __half* Bg = Bgp + s * 32;
#pragma unroll
        for (int j = 0; j < 4; ++j) {
            int id = t + j * 128;
            int row = id >> 2, c8 = (id & 3) * 8;
            cp16(s2u(st + row * 40 + c8), Ag + (size_t)row * K + c8);
            cp16(s2u(st + 5120 + row * 40 + c8), Bg + (size_t)row * K + c8);
        }
        asm volatile("cp.async.commit_group;");
    }

    for (int kb = 0; kb < NT; ++kb) {
        asm volatile("cp.async.wait_group %0;" :: "n"(STAGES - 2));
        __syncthreads();
        if (kb + STAGES - 1 < NT) {
            __half* st = hsm + ((kb + STAGES - 1) & (STAGES - 1)) * HSTG;
            const __half* Ag = Agp + (kb + STAGES - 1) * 32;
            const __half* Bg = Bgp + (kb + STAGES - 1) * 32;
#pragma unroll
            for (int j = 0; j < 4; ++j) {
                int id = t + j * 128;
                int row = id >> 2, c8 = (id & 3) * 8;
                cp16(s2u(st + row * 40 + c8), Ag + (size_t)row * K + c8);
                cp16(s2u(st + 5120 + row * 40 + c8), Bg + (size_t)row * K + c8);
            }
        }
        asm volatile("cp.async.commit_group;");

        const __half* Ab = hsm + (kb & (STAGES - 1)) * HSTG;
        const __half* Bb = Ab + 5120;
#pragma unroll
        for (int ks = 0; ks < 2; ++ks) {
            const int k0 = ks * 16;
            unsigned af[4][4], bf[8][2];
#pragma unroll
            for (int mt = 0; mt < 4; ++mt) {
                int row = wm * 64 + mt * 16 + fr;
                af[mt][0] = *(const uint32_t*)&Ab[row * 40 + k0 + 2 * fc];
                af[mt][1] = *(const uint32_t*)&Ab[(row + 8) * 40 + k0 + 2 * fc];
                af[mt][2] = *(const uint32_t*)&Ab[row * 40 + k0 + 2 * fc + 8];
                af[mt][3] = *(const uint32_t*)&Ab[(row + 8) * 40 + k0 + 2 * fc + 8];
            }
#pragma unroll
            for (int nt = 0; nt < 8; ++nt) {
                int col = wn * 64 + nt * 8 + fr;
                bf[nt][0] = *(const uint32_t*)&Bb[col * 40 + k0 + 2 * fc];
                bf[nt][1] = *(const uint32_t*)&Bb[col * 40 + k0 + 2 * fc + 8];
            }
#pragma unroll
            for (int mt = 0; mt < 4; ++mt)
#pragma unroll
                for (int nt = 0; nt < 8; ++nt)
                    mma_f16(acc[mt][nt], af[mt], bf[nt]);
        }
    }

    const int c2 = (lane & 3) * 2;
#pragma unroll
    for (int mt = 0; mt < 4; ++mt) {
        int row = m0 + wm * 64 + mt * 16 + fr;
#pragma unroll
        for (int nt = 0; nt < 8; ++nt) {
            int col = n0 + wn * 64 + nt * 8 + c2;
            size_t i0 = (size_t)row * N + col;
            size_t i1 = (size_t)(row + 8) * N + col;
            float b0 = bias[col], b1 = bias[col + 1];
            float v0 = acc[mt][nt][0] + b0, v1 = acc[mt][nt][1] + b1;
            float v2 = acc[mt][nt][2] + b0, v3 = acc[mt][nt][3] + b1;
            if (RES) {
                float2 r0 = *(const float2*)&Rsrc[i0];
                float2 r1 = *(const float2*)&Rsrc[i1];
                v0 += r0.x; v1 += r0.y; v2 += r1.x; v3 += r1.y;
            }
            if (RELU) { v0 = fmaxf(v0, 0.f); v1 = fmaxf(v1, 0.f); v2 = fmaxf(v2, 0.f); v3 = fmaxf(v3, 0.f); }
            if (OUTH) {
                __half* Ch = (__half*)Cv;
                *(__half2*)(Ch + i0) = __floats2half2_rn(v0, v1);
                *(__half2*)(Ch + i1) = __floats2half2_rn(v2, v3);
            } else {
                float* Cf = (float*)Cv;
                float2 o0 = {v0, v1}, o1 = {v2, v3};
                *(float2*)&Cf[i0] = o0;
                *(float2*)&Cf[i1] = o1;
            }
        }
    }
}

/* ---------------- fused flash attention: scores+softmax+AV on tensor cores ----- */
__global__ __launch_bounds__(128) void flash_attn_kernel(const __half* __restrict__ qkv,
                                                         const float* __restrict__ bias,
                                                         __half* __restrict__ o) {
    __shared__ __half Qs[64 * 104];
    __shared__ __half Ks[64 * 104];
    __shared__ __half VT[96 * 72];
    int bm = blockIdx.x, h = blockIdx.y;
    int t = threadIdx.x;
    int w = t >> 5, lane = t & 31;
    const __half* qg = qkv + (size_t)bm * 64 * QKVS + h * EE;
    const __half* kg = qg + 768;
    const __half* vg = qg + 1536;

    for (int i = t; i < 768; i += 128) {
        int r = i / 12, c = i % 12;
        *(uint4*)&Qs[r * 104 + c * 8] = *(const uint4*)(qg + (size_t)r * QKVS + c * 8);
        *(uint4*)&Ks[r * 104 + c * 8] = *(const uint4*)(kg + (size_t)r * QKVS + c * 8);
    }
    for (int i = t; i < 768; i += 128) {
        int s = i / 12, c = i % 12;
        uint4 raw = *(const uint4*)(vg + (size_t)s * QKVS + c * 8);
        const __half* hp = (const __half*)&raw;
#pragma unroll
        for (int j = 0; j < 8; ++j) VT[(c * 8 + j) * 72 + s] = hp[j];
    }
    __syncthreads();

    const int fr = lane >> 2, c2 = (lane & 3) * 2;
    const int mr = w * 16;
    float acc[8][4];
#pragma unroll
    for (int nt = 0; nt < 8; ++nt)
#pragma unroll
        for (int r = 0; r < 4; ++r) acc[nt][r] = 0.f;

#pragma unroll
    for (int kc = 0; kc < 6; ++kc) {
        unsigned a[4];
        const __half* qb = &Qs[(mr + fr) * 104 + kc * 16];
        a[0] = *(const uint32_t*)&qb[c2];
        a[1] = *(const uint32_t*)&qb[8 * 104 + c2];
        a[2] = *(const uint32_t*)&qb[c2 + 8];
        a[3] = *(const uint32_t*)&qb[8 * 104 + c2 + 8];
#pragma unroll
        for (int nt = 0; nt < 8; ++nt) {
            unsigned b[2];
            const __half* kb = &Ks[(nt * 8 + fr) * 104 + kc * 16];
            b[0] = *(const uint32_t*)&kb[c2];
            b[1] = *(const uint32_t*)&kb[c2 + 8];
            mma_f16(acc[nt], a, b);
        }
    }

    const float SCALE = 0.10206207261596575f;
    const int l0 = mr + fr;
    float mx0 = -1e30f, mx1 = -1e30f;
#pragma unroll
    for (int nt = 0; nt < 8; ++nt) {
        int s0 = nt * 8 + c2;
        acc[nt][0] = acc[nt][0] * SCALE + bias[(l0 * 64 + s0) * 8 + h];
        acc[nt][1] = acc[nt][1] * SCALE + bias[(l0 * 64 + s0 + 1) * 8 + h];
        acc[nt][2] = acc[nt][2] * SCALE + bias[((l0 + 8) * 64 + s0) * 8 + h];
        acc[nt][3] = acc[nt][3] * SCALE + bias[((l0 + 8) * 64 + s0 + 1) * 8 + h];
        mx0 = fmaxf(mx0, fmaxf(acc[nt][0], acc[nt][1]));
        mx1 = fmaxf(mx1, fmaxf(acc[nt][2], acc[nt][3]));
    }
    mx0 = fmaxf(mx0, __shfl_xor_sync(0xffffffffu, mx0, 1));
    mx0 = fmaxf(mx0, __shfl_xor_sync(0xffffffffu, mx0, 2));
    mx1 = fmaxf(mx1, __shfl_xor_sync(0xffffffffu, mx1, 1));
    mx1 = fmaxf(mx1, __shfl_xor_sync(0xffffffffu, mx1, 2));
    float sm0 = 0.f, sm1 = 0.f;
#pragma unroll
    for (int nt = 0; nt < 8; ++nt) {
        acc[nt][0] = expf(acc[nt][0] - mx0); sm0 += acc[nt][0];
        acc[nt][1] = expf(acc[nt][1] - mx0); sm0 += acc[nt][1];
        acc[nt][2] = expf(acc[nt][2] - mx1); sm1 += acc[nt][2];
        acc[nt][3] = expf(acc[nt][3] - mx1); sm1 += acc[nt][3];
    }
    sm0 += __shfl_xor_sync(0xffffffffu, sm0, 1);
    sm0 += __shfl_xor_sync(0xffffffffu, sm0, 2);
    sm1 += __shfl_xor_sync(0xffffffffu, sm1, 1);
    sm1 += __shfl_xor_sync(0xffffffffu, sm1, 2);
    float inv0 = 1.f / sm0, inv1 = 1.f / sm1;

    __half2 ph0[8], ph1[8];
#pragma unroll
    for (int nt = 0; nt < 8; ++nt) {
        ph0[nt] = __floats2half2_rn(acc[nt][0] * inv0, acc[nt][1] * inv0);
        ph1[nt] = __floats2half2_rn(acc[nt][2] * inv1, acc[nt][3] * inv1);
    }

    float oacc[12][4];
#pragma unroll
    for (int nt = 0; nt < 12; ++nt)
#pragma unroll
        for (int r = 0; r < 4; ++r) oacc[nt][r] = 0.f;

#pragma unroll
    for (int kc = 0; kc < 4; ++kc) {
        unsigned a[4];
        a[0] = *(const unsigned*)&ph0[2 * kc];
        a[1] = *(const unsigned*)&ph1[2 * kc];
        a[2] = *(const unsigned*)&ph0[2 * kc + 1];
        a[3] = *(const unsigned*)&ph1[2 * kc + 1];
#pragma unroll
        for (int nt = 0; nt < 12; ++nt) {
            unsigned b[2];
            const __half* vb = &VT[(nt * 8 + fr) * 72 + kc * 16];
            b[0] = *(const uint32_t*)&vb[c2];
            b[1] = *(const uint32_t*)&vb[c2 + 8];
            mma_f16(oacc[nt], a, b);
        }
    }

    __half* op = o + (size_t)bm * 64 * DD + h * EE;
#pragma unroll
    for (int nt = 0; nt < 12; ++nt) {
        int col = nt * 8 + c2;
        *(__half2*)&op[(size_t)l0 * DD + col] = __floats2half2_rn(oacc[nt][0], oacc[nt][1]);
        *(__half2*)&op[(size_t)(l0 + 8) * DD + col] = __floats2half2_rn(oacc[nt][2], oacc[nt][3]);
    }
}

/* ---------------- RevIN stats ---------------- */
__global__ void revin_stats_kernel(const float* __restrict__ x, float* __restrict__ mean,
                                   float* __restrict__ stdv) {
    int bm = blockIdx.x;
    int b = bm / MM, m = bm % MM;
    const float* xp = x + (size_t)b * LL * MM + m;
    float s = 0.f, s2 = 0.f;
    for (int l = threadIdx.x; l < LL; l += 256) {
        float v = xp[(size_t)l * MM];
        s += v; s2 += v * v;
    }
    __shared__ float sh0[256], sh1[256];
    sh0[threadIdx.x] = s; sh1[threadIdx.x] = s2;
    __syncthreads();
    for (int off = 128; off > 0; off >>= 1) {
        if (threadIdx.x < off) { sh0[threadIdx.x] += sh0[threadIdx.x + off]; sh1[threadIdx.x] += sh1[threadIdx.x + off]; }
        __syncthreads();
    }
    if (threadIdx.x == 0) {
        float mu = sh0[0] * (1.f / LL);
        float var = sh1[0] * (1.f / LL) - mu * mu;
        mean[bm] = mu;
        stdv[bm] = sqrtf(var + EPSF);
    }
}

/* ---------------- patches ---------------- */
__global__ void patches_kernel(const float* __restrict__ x, const float* __restrict__ mean,
                               const float* __restrict__ stdv, const float* __restrict__ rw,
                               const float* __restrict__ rb, float* __restrict__ patches) {
    int idx = blockIdx.x * 256 + threadIdx.x;
    int p = idx & 15;
    int n = (idx >> 4) & 63;
    int bm = idx >> 10;
    int m = bm % MM;
    int b = bm / MM;
    int l = n * 16 + p;
    float v = x[(size_t)b * LL * MM + (size_t)l * MM + m];
    v = (v - mean[bm]) / stdv[bm] * rw[m] + rb[m];
    patches[idx] = v;
}

/* ---------------- composed spectral transform ---------------- */
__global__ void computeT_kernel(const float* __restrict__ wr, const float* __restrict__ wi,
                                float* __restrict__ T) {
    int lay = blockIdx.x;
    __shared__ float Ur[32][64], Ui[32][64];
    const float* wrp = wr + (size_t)lay * FREQ * A2;
    const float* wip = wi + (size_t)lay * FREQ * A2;
    const float c0 = 6.28318530717958647692f / 64.f;
    for (int e = threadIdx.x; e < 32 * 64; e += 256) {
        int d = e >> 6, n = e & 63;
        float sr = 0.f, si = 0.f;
        for (int kf = 0; kf < FREQ; ++kf) {
            float ang = c0 * (float)(kf * n);
            float cv, sv;
            sincosf(ang, &sv, &cv);
            sr += wrp[kf * A2 + d] * cv;
            si += wip[kf * A2 + d] * (-sv);
        }
        Ur[d][n] = sr; Ui[d][n] = si;
    }
    __syncthreads();
    for (int e = threadIdx.x; e < 64 * 64; e += 256) {
        int a = e >> 6, n = e & 63;
        float tval = Ur[0][n];
        for (int d = 1; d < 32; ++d) {
            float ang = c0 * (float)(d * a);
            float cv, sv;
            sincosf(ang, &sv, &cv);
            tval += 2.f * (Ur[d][n] * cv - Ui[d][n] * sv);
        }
        T[lay * 4096 + e] = tval * (1.f / 64.f);
    }
}

/* ---------------- instance-norm stats ---------------- */
__global__ void pn_stats_kernel(const float* __restrict__ patches, float* __restrict__ mu,
                                float* __restrict__ rv) {
    int idx = blockIdx.x * 256 + threadIdx.x;
    int b = idx >> 10;
    int np = idx & 1023;
    const float* pp = patches + (size_t)b * 21504 + np;
    float s = 0.f, s2 = 0.f;
#pragma unroll
    for (int m = 0; m < MM; ++m) { float v = pp[m * 1024]; s += v; s2 += v * v; }
    float m0 = s * (1.f / MM);
    float var = s2 * (1.f / MM) - m0 * m0;
    mu[idx] = m0;
    rv[idx] = rsqrtf(var + EPSF);
}

/* ---------------- spectral mixing ---------------- */
__global__ void spect_kernel(const float* __restrict__ patches, const float* __restrict__ mu,
                             const float* __restrict__ rv, const float* __restrict__ g,
                             const float* __restrict__ be, const float* __restrict__ T,
                             float* __restrict__ ad) {
    int idx = blockIdx.x * 256 + threadIdx.x;
    int p = idx & 15;
    int a = (idx >> 4) & 63;
    int bm = idx >> 10;
    int m = bm % MM;
    int b = bm / MM;
    float gm = g[m], bm_ = be[m];
    const float* pp  = patches + (size_t)bm * 1024 + p;
    const float* mup = mu + b * 1024 + p;
    const float* rvp = rv + b * 1024 + p;
    const float* Tp  = T + a * 64;
    float acc = 0.f;
#pragma unroll 8
    for (int n = 0; n < 64; ++n) {
        float pn = (pp[n * 16] - mup[n * 16]) * rvp[n * 16] * gm + bm_;
        acc += Tp[n] * pn;
    }
    ad[idx] = acc;
}

/* ---------------- embeddings ---------------- */
template<int ADD>
__global__ __launch_bounds__(256) void embed_kernel(const float* __restrict__ src,
                                                    const float* __restrict__ Hin,
                                                    const float* __restrict__ inw,
                                                    const float* __restrict__ inb,
                                                    float* __restrict__ out32,
                                                    __half* __restrict__ out16) {
    __shared__ float ps[1024];
    int blk = blockIdx.x;
    int t = threadIdx.x;
    const float4* sp = (const float4*)(src + (size_t)blk * 1024);
    ((float4*)ps)[t] = sp[t];
    float w[3][16], bb[3];
#pragma unroll
    for (int j = 0; j < 3; ++j) {
        int c = t + 256 * j;
        bb[j] = inb[c];
#pragma unroll
        for (int p4 = 0; p4 < 4; ++p4) {
            float4 wv = *(const float4*)(inw + (size_t)c * 16 + p4 * 4);
            w[j][p4 * 4] = wv.x; w[j][p4 * 4 + 1] = wv.y; w[j][p4 * 4 + 2] = wv.z; w[j][p4 * 4 + 3] = wv.w;
        }
    }
    __syncthreads();
    size_t rowbase = (size_t)blk * 64 * DD;
    for (int r = 0; r < 64; ++r) {
        float pr[16];
#pragma unroll
        for (int p4 = 0; p4 < 4; ++p4) {
            float4 pv = *(const float4*)&ps[r * 16 + p4 * 4];
            pr[p4 * 4] = pv.x; pr[p4 * 4 + 1] = pv.y; pr[p4 * 4 + 2] = pv.z; pr[p4 * 4 + 3] = pv.w;
        }
        size_t ro = rowbase + (size_t)r * DD;
#pragma unroll
        for (int j = 0; j < 3; ++j) {
            float acc = bb[j];
            if (ADD) acc += Hin[ro + t + 256 * j];
#pragma unroll
            for (int p = 0; p < 16; ++p) acc = fmaf(pr[p], w[j][p], acc);
            out32[ro + t + 256 * j] = acc;
            if (ADD) out16[ro + t + 256 * j] = __float2half(acc);
        }
    }
}

/* ---------------- batchnorm ---------------- */
__global__ void zero_kernel(float* __restrict__ p, int n) {
    int idx = blockIdx.x * 256 + threadIdx.x;
    if (idx < n) p[idx] = 0.f;
}

__global__ void bn_reduce_kernel(const float* __restrict__ X, float* __restrict__ sum,
                                 float* __restrict__ sq) {
    int r0 = blockIdx.x * 128;
    float s[3] = {0.f, 0.f, 0.f}, q[3] = {0.f, 0.f, 0.f};
    for (int r = 0; r < 128; ++r) {
        const float* xp = X + (size_t)(r0 + r) * DD;
#pragma unroll
        for (int j = 0; j < 3; ++j) {
            float v = xp[threadIdx.x + j * 256];
            s[j] += v; q[j] += v * v;
        }
    }
#pragma unroll
    for (int j = 0; j < 3; ++j) {
        atomicAdd(&sum[threadIdx.x + j * 256], s[j]);
        atomicAdd(&sq[threadIdx.x + j * 256], q[j]);
    }
}

template<int WH>
__global__ void bn_apply_kernel(float* __restrict__ X, const float* __restrict__ sum,
                                const float* __restrict__ sq, const float* __restrict__ g,
                                const float* __restrict__ be, __half* __restrict__ Xh) {
    int idx = blockIdx.x * 256 + threadIdx.x;
    int c = idx % DD;
    const float inv_n = 1.f / (float)ROWS;
    float mean = sum[c] * inv_n;
    float var = sq[c] * inv_n - mean * mean;
    float v = (X[idx] - mean) * rsqrtf(var + EPSF) * g[c] + be[c];
    X[idx] = v;
    if (WH) Xh[idx] = __float2half(v);
}

/* fused bn2 + final norm (layer 3) */
__global__ void bn_apply_final_kernel(float* __restrict__ X, const float* __restrict__ sum,
                                      const float* __restrict__ sq,
                                      const float* __restrict__ g2, const float* __restrict__ b2,
                                      const float* __restrict__ g3, const float* __restrict__ b3) {
    int idx = blockIdx.x * 256 + threadIdx.x;
    int c = idx % DD;
    const float inv_n = 1.f / (float)ROWS;
    float mean = sum[c] * inv_n;
    float var = sq[c] * inv_n - mean * mean;
    float r = rsqrtf(var + EPSF);
    float s = g2[c] * r;
    float xv = (X[idx] - mean) * s;
    float r2 = rsqrtf(s * s * var + EPSF);
    X[idx] = xv * r2 * g3[c] + b3[c];
}

/* ---------------- final projection ---------------- */
__global__ void final_gemm_kernel(const float* __restrict__ hbuf, const float* __restrict__ ow,
                                  float* __restrict__ osmall) {
    __shared__ float hs[8 * 1024];
    int row0 = blockIdx.x * 8;
    int k0 = blockIdx.y * 1024;
    for (int j = threadIdx.x; j < 2048; j += 128) {
        int r = j >> 8, kq = j & 255;
        *(float4*)&hs[r * 1024 + kq * 4] =
            *(const float4*)&hbuf[(size_t)(row0 + r) * 49152 + k0 + kq * 4];
    }
    __syncthreads();
    int p = threadIdx.x;
    if (p < PREDN) {
        float acc[8] = {0.f, 0.f, 0.f, 0.f, 0.f, 0.f, 0.f, 0.f};
        const float* wp = ow + (size_t)p * 49152 + k0;
        for (int kq = 0; kq < 256; ++kq) {
            float4 w4 = *(const float4*)(wp + kq * 4);
#pragma unroll
            for (int r = 0; r < 8; ++r) {
                const float* hr = &hs[r * 1024 + kq * 4];
                acc[r] += hr[0] * w4.x + hr[1] * w4.y + hr[2] * w4.z + hr[3] * w4.w;
            }
        }
#pragma unroll
        for (int r = 0; r < 8; ++r) atomicAdd(&osmall[(row0 + r) * PREDN + p], acc[r]);
    }
}

/* ---------------- de-norm ---------------- */
__global__ void denorm_kernel(const float* __restrict__ osmall, const float* __restrict__ outb,
                              const float* __restrict__ rw, const float* __restrict__ rb,
                              const float* __restrict__ mean, const float* __restrict__ stdv,
                              float* __restrict__ out) {
    int idx = blockIdx.x * 256 + threadIdx.x;
    int m = idx % MM;
    int pr = (idx / MM) % PREDN;
    int b = idx / (MM * PREDN);
    int bm = b * MM + m;
    float v = osmall[bm * PREDN + pr] + outb[pr];
    v = (v - rb[m]) / (rw[m] + 1e-10f);
    out[idx] = v * stdv[bm] + mean[bm];
}

/* ---------------- launcher ---------------- */
extern "C" void kernel_launch(void* const* d_in, const int* in_sizes, int n_in,
                              void* d_out, int out_size) {
    const float* x         = (const float*)d_in[0];
    const float* attn_bias = (const float*)d_in[1];
    const float* revin_w   = (const float*)d_in[2];
    const float* revin_b   = (const float*)d_in[3];
    const float* in_w      = (const float*)d_in[4];
    const float* in_b      = (const float*)d_in[5];
    const float* ln1_g     = (const float*)d_in[6];
    const float* ln1_b     = (const float*)d_in[7];
    const float* spect_wr  = (const float*)d_in[8];
    const float* spect_wi  = (const float*)d_in[9];
    const float* Wq        = (const float*)d_in[10];
    const float* bq        = (const float*)d_in[11];
    const float* Wk        = (const float*)d_in[12];
    const float* bk        = (const float*)d_in[13];
    const float* Wv        = (const float*)d_in[14];
    const float* bv        = (const float*)d_in[15];
    const float* Wo        = (const float*)d_in[16];
    const float* bo        = (const float*)d_in[17];
    const float* c1_w      = (const float*)d_in[18];
    const float* c1_b      = (const float*)d_in[19];
    const float* c2_w      = (const float*)d_in[20];
    const float* c2_b      = (const float*)d_in[21];
    const float* bn1_g     = (const float*)d_in[22];
    const float* bn1_b     = (const float*)d_in[23];
    const float* bn2_g     = (const float*)d_in[24];
    const float* bn2_b     = (const float*)d_in[25];
    const float* norm_g    = (const float*)d_in[26];
    const float* norm_b    = (const float*)d_in[27];
    const float* out_w     = (const float*)d_in[28];
    const float* out_b     = (const float*)d_in[29];

    float* base = nullptr;
    cudaGetSymbolAddress((void**)&base, g_buf);
    float* mean   = base + OFF_MEAN;
    float* stdv   = base + OFF_STD;
    float* patch  = base + OFF_PATCH;
    float* Tm     = base + OFF_T;
    float* mu     = base + OFF_MU;
    float* rv     = base + OFF_RV;
    float* ad     = base + OFF_AD;
    float* bnsum  = base + OFF_BNSUM;
    float* bnsq   = base + OFF_BNSQ;
    float* osmall = base + OFF_OSMALL;
    float* h      = base + OFF_H;
    float* y      = base + OFF_Y;
    __half* qkvh  = (__half*)(base + OFF_QKVH);
    __half* y16   = (__half*)(base + OFF_Y16);
    __half* o16   = (__half*)(base + OFF_O16);
    __half* f4h   = (__half*)(base + OFF_F4H);
    __half* wh    = (__half*)(base + OFF_WH);
    __half* WHqkv = wh;
    __half* WHo   = wh + 5308416u;
    __half* WH1   = wh + 7077888u;
    __half* WH2   = wh + 14155776u;
    float* bqkv   = base + OFF_BQKV;

    cudaFuncSetAttribute(hgemm<0, 0, 1>, cudaFuncAttributeMaxDynamicSharedMemorySize, GSMH);
    cudaFuncSetAttribute(hgemm<0, 1, 0>, cudaFuncAttributeMaxDynamicSharedMemorySize, GSMH);
    cudaFuncSetAttribute(hgemm<1, 0, 1>, cudaFuncAttributeMaxDynamicSharedMemorySize, GSMH);

    const int TPB = 256;
    const int G_ED = (ROWS * DD) / TPB;

    wconv_qkv_h_kernel<<<1769472 / TPB, TPB>>>(Wq, WHqkv, 0);
    wconv_qkv_h_kernel<<<1769472 / TPB, TPB>>>(Wk, WHqkv, 1);
    wconv_qkv_h_kernel<<<1769472 / TPB, TPB>>>(Wv, WHqkv, 2);
    wconv_h_kernel<<<1769472 / TPB, TPB>>>(Wo, WHo, 1769472);
    wconv_h_kernel<<<7077888 / TPB, TPB>>>(c1_w, WH1, 7077888);
    wconv_h_kernel<<<7077888 / TPB, TPB>>>(c2_w, WH2, 7077888);
    bpack_kernel<<<27, TPB>>>(bq, bk, bv, bqkv);

    revin_stats_kernel<<<BMC, TPB>>>(x, mean, stdv);
    patches_kernel<<<344064 / TPB, TPB>>>(x, mean, stdv, revin_w, revin_b, patch);
    computeT_kernel<<<NLAYER, TPB>>>(spect_wr, spect_wi, Tm);
    embed_kernel<0><<<BMC, TPB>>>(patch, nullptr, in_w, in_b, h, nullptr);

    dim3 gQKV(QKVS / 128, ROWS / 128);
    dim3 gP(DD / 128, ROWS / 128);
    dim3 gF1(FF4 / 128, ROWS / 128);
    dim3 gFA(BMC, HH);

    for (int i = 0; i < NLAYER; ++i) {
        pn_stats_kernel<<<16384 / TPB, TPB>>>(patch, mu, rv);
        spect_kernel<<<344064 / TPB, TPB>>>(patch, mu, rv, ln1_g + i * MM, ln1_b + i * MM,
                                            Tm + i * 4096, ad);
        embed_kernel<1><<<BMC, TPB>>>(ad, h, in_w, in_b, y, y16);

        hgemm<0, 0, 1><<<gQKV, 128, GSMH>>>(y16, WHqkv + (size_t)i * 1769472u,
                                            bqkv + i * QKVS, nullptr, qkvh, ROWS, QKVS, DD);

        flash_attn_kernel<<<gFA, 128>>>(qkvh, attn_bias, o16);

        hgemm<0, 1, 0><<<gP, 128, GSMH>>>(o16, WHo + (size_t)i * DD * DD, bo + i * DD,
                                          y, y, ROWS, DD, DD);

        zero_kernel<<<6, TPB>>>(bnsum, 1536);
        bn_reduce_kernel<<<ROWS / 128, TPB>>>(y, bnsum, bnsq);
        bn_apply_kernel<1><<<G_ED, TPB>>>(y, bnsum, bnsq, bn1_g + i * DD, bn1_b + i * DD, y16);

        hgemm<1, 0, 1><<<gF1, 128, GSMH>>>(y16, WH1 + (size_t)i * FF4 * DD, c1_b + i * FF4,
                                           nullptr, f4h, ROWS, FF4, DD);
        hgemm<0, 1, 0><<<gP, 128, GSMH>>>(f4h, WH2 + (size_t)i * DD * FF4, c2_b + i * DD,
                                          y, h, ROWS, DD, FF4);

        zero_kernel<<<6, TPB>>>(bnsum, 1536);
        bn_reduce_kernel<<<ROWS / 128, TPB>>>(h, bnsum, bnsq);
        if (i < NLAYER - 1) {
            bn_apply_kernel<0><<<G_ED, TPB>>>(h, bnsum, bnsq, bn2_g + i * DD, bn2_b + i * DD, nullptr);
        } else {
            bn_apply_final_kernel<<<G_ED, TPB>>>(h, bnsum, bnsq, bn2_g + i * DD, bn2_b + i * DD,
                                                 norm_g, norm_b);
        }
    }

    zero_kernel<<<32256 / TPB, TPB>>>(osmall, 32256);
    final_gemm_kernel<<<dim3(BMC / 8, 48), 128>>>(h, out_w, osmall);
    denorm_kernel<<<32256 / TPB, TPB>>>(osmall, out_b, revin_w, revin_b, mean, stdv,
                                        (float*)d_out);
}

// round 12
// speedup vs baseline: 1.2623x; 1.1164x over previous
#include <cuda_runtime.h>
#include <cuda_fp16.h>
#include <math.h>
#include <stdint.h>

#define BB 16
#define LL 1024
#define MM 21
#define PP 16
#define NN 64
#define DD 768
#define HH 8
#define EE 96
#define FF4 3072
#define NLAYER 3
#define FREQ 33
#define A2 32
#define PREDN 96
#define BMC (BB*MM)          /* 336 */
#define ROWS (BMC*NN)        /* 21504 */
#define EPSF 1e-5f
#define QKVS 2304

/* ---------------- scratch layout (float units) ---------------- */
#define OFF_MEAN   0u
#define OFF_STD    512u
#define OFF_PATCH  1024u
#define OFF_T      345088u
#define OFF_MU     357376u
#define OFF_RV     373760u
#define OFF_AD     390144u
#define OFF_BNSUM  734208u
#define OFF_BNSQ   734976u
#define OFF_OSMALL 735744u
#define OFF_H      768000u
#define OFF_Y      (OFF_H + 16515072u)
#define OFF_QKVH   (OFF_Y + 16515072u)
#define OFF_SC     (OFF_QKVH + 24772608u)
#define OFF_Y16    (OFF_SC + 11010048u)
#define OFF_O16    (OFF_Y16 + 8257536u)
#define OFF_F4H    (OFF_O16 + 8257536u)
#define OFF_WH     (OFF_F4H + 33030144u)
#define OFF_BQKV   (OFF_WH + 10616832u)
#define TOTAL_F    (OFF_BQKV + 8192u)

__device__ float g_buf[TOTAL_F];

/* ================= helpers ================= */
__device__ __forceinline__ uint32_t s2u(const void* p) {
    uint32_t a;
    asm("{ .reg .u64 t; cvta.to.shared.u64 t, %1; cvt.u32.u64 %0, t; }" : "=r"(a) : "l"(p));
    return a;
}
__device__ __forceinline__ void mma_f16(float* d, const unsigned* a, const unsigned* b) {
    asm volatile("mma.sync.aligned.m16n8k16.row.col.f32.f16.f16.f32 "
                 "{%0,%1,%2,%3},{%4,%5,%6,%7},{%8,%9},{%0,%1,%2,%3};"
                 : "+f"(d[0]), "+f"(d[1]), "+f"(d[2]), "+f"(d[3])
                 : "r"(a[0]), "r"(a[1]), "r"(a[2]), "r"(a[3]), "r"(b[0]), "r"(b[1]));
}
__device__ __forceinline__ void cp16(uint32_t saddr, const void* g) {
    asm volatile("cp.async.ca.shared.global [%0], [%1], 16;" :: "r"(saddr), "l"(g));
}
__device__ __forceinline__ void ldsm4(unsigned* r, uint32_t addr) {
    asm volatile("ldmatrix.sync.aligned.m8n8.x4.shared.b16 {%0,%1,%2,%3}, [%4];"
                 : "=r"(r[0]), "=r"(r[1]), "=r"(r[2]), "=r"(r[3]) : "r"(addr));
}

/* ---------------- weight fp16 conversion ---------------- */
__global__ void wconv_h_kernel(const float* __restrict__ in, __half* __restrict__ out, int n) {
    int idx = blockIdx.x * 256 + threadIdx.x;
    if (idx < n) out[idx] = __float2half(in[idx]);
}
__global__ void wconv_qkv_h_kernel(const float* __restrict__ in, __half* __restrict__ out,
                                   int part) {
    int idx = blockIdx.x * 256 + threadIdx.x;
    int lay = idx / 589824, w = idx % 589824;
    out[(size_t)lay * 1769472 + (size_t)part * 589824 + w] = __float2half(in[idx]);
}
__global__ void bpack_kernel(const float* __restrict__ bq, const float* __restrict__ bk,
                             const float* __restrict__ bv, float* __restrict__ out) {
    int idx = blockIdx.x * 256 + threadIdx.x;
    if (idx >= NLAYER * QKVS) return;
    int lay = idx / QKVS, c = idx % QKVS;
    float v;
    if (c < 768) v = bq[lay * 768 + c];
    else if (c < 1536) v = bk[lay * 768 + c - 768];
    else v = bv[lay * 768 + c - 1536];
    out[idx] = v;
}

/* =========== cp.async 4-stage fp16 mma GEMM with ldmatrix fragments =========== */
#define STAGES 4
#define HSTG   10240
#define GSMH   (STAGES * HSTG * 2)         /* 81920 bytes */

template<int RELU, int RES, int OUTH>
__global__ __launch_bounds__(128, 2) void hgemm(const __half* __restrict__ A,
                                                const __half* __restrict__ W,
                                                const float* __restrict__ bias,
                                                const float* __restrict__ Rsrc,
                                                void* __restrict__ Cv,
                                                int M, int N, int K) {
    extern __shared__ __half hsm[];
    const int t = threadIdx.x;
    const int wid = t >> 5, lane = t & 31;
    const int wm = wid >> 1, wn = wid & 1;
    const int m0 = blockIdx.y * 128, n0 = blockIdx.x * 128;
    const int fr = lane >> 2;
    const uint32_t sbase = s2u(hsm);

    /* ldmatrix per-thread address components */
    const int grp = lane >> 3, wi = lane & 7;
    const uint32_t aoff = ((uint32_t)((wm * 64 + (grp & 1) * 8 + wi) * 40 + (grp >> 1) * 8)) * 2u;
    const uint32_t boff = 10240u + ((uint32_t)((wn * 64 + (grp >> 1) * 8 + wi) * 40 + (grp & 1) * 8)) * 2u;

    const __half* Agp = A + (size_t)m0 * K;
    const __half* Bgp = W + (size_t)n0 * K;

    float acc[4][8][4];
#pragma unroll
    for (int i = 0; i < 4; ++i)
#pragma unroll
        for (int j = 0; j < 8; ++j)
#pragma unroll
            for (int r = 0; r < 4; ++r) acc[i][j][r] = 0.f;

    const int NT = K >> 5;

#pragma unroll
    for (int s = 0; s < STAGES - 1; ++s) {
        __half* st = hsm + s * HSTG;
        const __half* Ag = Agp + s * 32;
        const __half* Bg = Bgp + s * 32;
#pragma unroll
        for (int j = 0; j < 4; ++j) {
            int id = t + j * 128;
            int row = id >> 2, c8 = (id & 3) * 8;
            cp16(s2u(st + row * 40 + c8), Ag + (size_t)row * K + c8);
            cp16(s2u(st + 5120 + row * 40 + c8), Bg + (size_t)row * K + c8);
        }
        asm volatile("cp.async.commit_group;");
    }

    for (int kb = 0; kb < NT; ++kb) {
        asm volatile("cp.async.wait_group %0;" :: "n"(STAGES - 2));
        __syncthreads();
        if (kb + STAGES - 1 < NT) {
            __half* st = hsm + ((kb + STAGES - 1) & (STAGES - 1)) * HSTG;
            const __half* Ag = Agp + (kb + STAGES - 1) * 32;
            const __half* Bg = Bgp + (kb + STAGES - 1) * 32;
#pragma unroll
            for (int j = 0; j < 4; ++j) {
                int id = t + j * 128;
                int row = id >> 2, c8 = (id & 3) * 8;
                cp16(s2u(st + row * 40 + c8), Ag + (size_t)row * K + c8);
                cp16(s2u(st + 5120 + row * 40 + c8), Bg + (size_t)row * K + c8);
            }
        }
        asm volatile("cp.async.commit_group;");

        const uint32_t stg = sbase + (uint32_t)(kb & (STAGES - 1)) * 20480u;
#pragma unroll
        for (int ks = 0; ks < 2; ++ks) {
            const uint32_t kso = (uint32_t)ks * 32u;
            unsigned af[4][4], bfr[16];
            uint32_t ab = stg + aoff + kso;
#pragma unroll
            for (int mt = 0; mt < 4; ++mt)
                ldsm4(af[mt], ab + (uint32_t)mt * 1280u);
            uint32_t bb = stg + boff + kso;
#pragma unroll
            for (int nt2 = 0; nt2 < 4; ++nt2)
                ldsm4(&bfr[nt2 * 4], bb + (uint32_t)nt2 * 1280u);
#pragma unroll
            for (int mt = 0; mt < 4; ++mt)
#pragma unroll
                for (int nt = 0; nt < 8; ++nt)
                    mma_f16(acc[mt][nt], af[mt], &bfr[nt * 2]);
        }
    }

    const int c2 = (lane & 3) * 2;
#pragma unroll
    for (int mt = 0; mt < 4; ++mt) {
        int row = m0 + wm * 64 + mt * 16 + fr;
#pragma unroll
        for (int nt = 0; nt < 8; ++nt) {
            int col = n0 + wn * 64 + nt * 8 + c2;
            size_t i0 = (size_t)row * N + col;
            size_t i1 = (size_t)(row + 8) * N + col;
            float b0 = bias[col], b1 = bias[col + 1];
            float v0 = acc[mt][nt][0] + b0, v1 = acc[mt][nt][1] + b1;
            float v2 = acc[mt][nt][2] + b0, v3 = acc[mt][nt][3] + b1;
            if (RES) {
                float2 r0 = *(const float2*)&Rsrc[i0];
                float2 r1 = *(const float2*)&Rsrc[i1];
                v0 += r0.x; v1 += r0.y; v2 += r1.x; v3 += r1.y;
            }
            if (RELU) { v0 = fmaxf(v0, 0.f); v1 = fmaxf(v1, 0.f); v2 = fmaxf(v2, 0.f); v3 = fmaxf(v3, 0.f); }
            if (OUTH) {
                __half* Ch = (__half*)Cv;
                *(__half2*)(Ch + i0) = __floats2half2_rn(v0, v1);
                *(__half2*)(Ch + i1) = __floats2half2_rn(v2, v3);
            } else {
                float* Cf = (float*)Cv;
                float2 o0 = {v0, v1}, o1 = {v2, v3};
                *(float2*)&Cf[i0] = o0;
                *(float2*)&Cf[i1] = o1;
            }
        }
    }
}

/* ---------------- fused flash attention ---------------- */
__global__ __launch_bounds__(128) void flash_attn_kernel(const __half* __restrict__ qkv,
                                                         const float* __restrict__ bias,
                                                         __half* __restrict__ o) {
    __shared__ __half Qs[64 * 104];
    __shared__ __half Ks[64 * 104];
    __shared__ __half VT[96 * 72];
    int bm = blockIdx.x, h = blockIdx.y;
    int t = threadIdx.x;
    int w = t >> 5, lane = t & 31;
    const __half* qg = qkv + (size_t)bm * 64 * QKVS + h * EE;
    const __half* kg = qg + 768;
    const __half* vg = qg + 1536;

    for (int i = t; i < 768; i += 128) {
        int r = i / 12, c = i % 12;
        *(uint4*)&Qs[r * 104 + c * 8] = *(const uint4*)(qg + (size_t)r * QKVS + c * 8);
        *(uint4*)&Ks[r * 104 + c * 8] = *(const uint4*)(kg + (size_t)r * QKVS + c * 8);
    }
    for (int i = t; i < 768; i += 128) {
        int s = i / 12, c = i % 12;
        uint4 raw = *(const uint4*)(vg + (size_t)s * QKVS + c * 8);
        const __half* hp = (const __half*)&raw;
#pragma unroll
        for (int j = 0; j < 8; ++j) VT[(c * 8 + j) * 72 + s] = hp[j];
    }
    __syncthreads();

    const int fr = lane >> 2, c2 = (lane & 3) * 2;
    const int mr = w * 16;
    float acc[8][4];
#pragma unroll
    for (int nt = 0; nt < 8; ++nt)
#pragma unroll
        for (int r = 0; r < 4; ++r) acc[nt][r] = 0.f;

#pragma unroll
    for (int kc = 0; kc < 6; ++kc) {
        unsigned a[4];
        const __half* qb = &Qs[(mr + fr) * 104 + kc * 16];
        a[0] = *(const uint32_t*)&qb[c2];
        a[1] = *(const uint32_t*)&qb[8 * 104 + c2];
        a[2] = *(const uint32_t*)&qb[c2 + 8];
        a[3] = *(const uint32_t*)&qb[8 * 104 + c2 + 8];
#pragma unroll
        for (int nt = 0; nt < 8; ++nt) {
            unsigned b[2];
            const __half* kb = &Ks[(nt * 8 + fr) * 104 + kc * 16];
            b[0] = *(const uint32_t*)&kb[c2];
            b[1] = *(const uint32_t*)&kb[c2 + 8];
            mma_f16(acc[nt], a, b);
        }
    }

    const float SCALE = 0.10206207261596575f;
    const int l0 = mr + fr;
    float mx0 = -1e30f, mx1 = -1e30f;
#pragma unroll
    for (int nt = 0; nt < 8; ++nt) {
        int s0 = nt * 8 + c2;
        acc[nt][0] = acc[nt][0] * SCALE + bias[(l0 * 64 + s0) * 8 + h];
        acc[nt][1] = acc[nt][1] * SCALE + bias[(l0 * 64 + s0 + 1) * 8 + h];
        acc[nt][2] = acc[nt][2] * SCALE + bias[((l0 + 8) * 64 + s0) * 8 + h];
        acc[nt][3] = acc[nt][3] * SCALE + bias[((l0 + 8) * 64 + s0 + 1) * 8 + h];
        mx0 = fmaxf(mx0, fmaxf(acc[nt][0], acc[nt][1]));
        mx1 = fmaxf(mx1, fmaxf(acc[nt][2], acc[nt][3]));
    }
    mx0 = fmaxf(mx0, __shfl_xor_sync(0xffffffffu, mx0, 1));
    mx0 = fmaxf(mx0, __shfl_xor_sync(0xffffffffu, mx0, 2));
    mx1 = fmaxf(mx1, __shfl_xor_sync(0xffffffffu, mx1, 1));
    mx1 = fmaxf(mx1, __shfl_xor_sync(0xffffffffu, mx1, 2));
    float sm0 = 0.f, sm1 = 0.f;
#pragma unroll
    for (int nt = 0; nt < 8; ++nt) {
        acc[nt][0] = expf(acc[nt][0] - mx0); sm0 += acc[nt][0];
        acc[nt][1] = expf(acc[nt][1] - mx0); sm0 += acc[nt][1];
        acc[nt][2] = expf(acc[nt][2] - mx1); sm1 += acc[nt][2];
        acc[nt][3] = expf(acc[nt][3] - mx1); sm1 += acc[nt][3];
    }
    sm0 += __shfl_xor_sync(0xffffffffu, sm0, 1);
    sm0 += __shfl_xor_sync(0xffffffffu, sm0, 2);
    sm1 += __shfl_xor_sync(0xffffffffu, sm1, 1);
    sm1 += __shfl_xor_sync(0xffffffffu, sm1, 2);
    float inv0 = 1.f / sm0, inv1 = 1.f / sm1;

    __half2 ph0[8], ph1[8];
#pragma unroll
    for (int nt = 0; nt < 8; ++nt) {
        ph0[nt] = __floats2half2_rn(acc[nt][0] * inv0, acc[nt][1] * inv0);
        ph1[nt] = __floats2half2_rn(acc[nt][2] * inv1, acc[nt][3] * inv1);
    }

    float oacc[12][4];
#pragma unroll
    for (int nt = 0; nt < 12; ++nt)
#pragma unroll
        for (int r = 0; r < 4; ++r) oacc[nt][r] = 0.f;

#pragma unroll
    for (int kc = 0; kc < 4; ++kc) {
        unsigned a[4];
        a[0] = *(const unsigned*)&ph0[2 * kc];
        a[1] = *(const unsigned*)&ph1[2 * kc];
        a[2] = *(const unsigned*)&ph0[2 * kc + 1];
        a[3] = *(const unsigned*)&ph1[2 * kc + 1];
#pragma unroll
        for (int nt = 0; nt < 12; ++nt) {
            unsigned b[2];
            const __half* vb = &VT[(nt * 8 + fr) * 72 + kc * 16];
            b[0] = *(const uint32_t*)&vb[c2];
            b[1] = *(const uint32_t*)&vb[c2 + 8];
            mma_f16(oacc[nt], a, b);
        }
    }

    __half* op = o + (size_t)bm * 64 * DD + h * EE;
#pragma unroll
    for (int nt = 0; nt < 12; ++nt) {
        int col = nt * 8 + c2;
        *(__half2*)&op[(size_t)l0 * DD + col] = __floats2half2_rn(oacc[nt][0], oacc[nt][1]);
        *(__half2*)&op[(size_t)(l0 + 8) * DD + col] = __floats2half2_rn(oacc[nt][2], oacc[nt][3]);
    }
}

/* ---------------- RevIN stats ---------------- */
__global__ void revin_stats_kernel(const float* __restrict__ x, float* __restrict__ mean,
                                   float* __restrict__ stdv) {
    int bm = blockIdx.x;
    int b = bm / MM, m = bm % MM;
    const float* xp = x + (size_t)b * LL * MM + m;
    float s = 0.f, s2 = 0.f;
    for (int l = threadIdx.x; l < LL; l += 256) {
        float v = xp[(size_t)l * MM];
        s += v; s2 += v * v;
    }
    __shared__ float sh0[256], sh1[256];
    sh0[threadIdx.x] = s; sh1[threadIdx.x] = s2;
    __syncthreads();
    for (int off = 128; off > 0; off >>= 1) {
        if (threadIdx.x < off) { sh0[threadIdx.x] += sh0[threadIdx.x + off]; sh1[threadIdx.x] += sh1[threadIdx.x + off]; }
        __syncthreads();
    }
    if (threadIdx.x == 0) {
        float mu = sh0[0] * (1.f / LL);
        float var = sh1[0] * (1.f / LL) - mu * mu;
        mean[bm] = mu;
        stdv[bm] = sqrtf(var + EPSF);
    }
}

/* ---------------- patches ---------------- */
__global__ void patches_kernel(const float* __restrict__ x, const float* __restrict__ mean,
                               const float* __restrict__ stdv, const float* __restrict__ rw,
                               const float* __restrict__ rb, float* __restrict__ patches) {
    int idx = blockIdx.x * 256 + threadIdx.x;
    int p = idx & 15;
    int n = (idx >> 4) & 63;
    int bm = idx >> 10;
    int m = bm % MM;
    int b = bm / MM;
    int l = n * 16 + p;
    float v = x[(size_t)b * LL * MM + (size_t)l * MM + m];
    v = (v - mean[bm]) / stdv[bm] * rw[m] + rb[m];
    patches[idx] = v;
}

/* ---------------- composed spectral transform ---------------- */
__global__ void computeT_kernel(const float* __restrict__ wr, const float* __restrict__ wi,
                                float* __restrict__ T) {
    int lay = blockIdx.x;
    __shared__ float Ur[32][64], Ui[32][64];
    const float* wrp = wr + (size_t)lay * FREQ * A2;
    const float* wip = wi + (size_t)lay * FREQ * A2;
    const float c0 = 6.28318530717958647692f / 64.f;
    for (int e = threadIdx.x; e < 32 * 64; e += 256) {
        int d = e >> 6, n = e & 63;
        float sr = 0.f, si = 0.f;
        for (int kf = 0; kf < FREQ; ++kf) {
            float ang = c0 * (float)(kf * n);
            float cv, sv;
            sincosf(ang, &sv, &cv);
            sr += wrp[kf * A2 + d] * cv;
            si += wip[kf * A2 + d] * (-sv);
        }
        Ur[d][n] = sr; Ui[d][n] = si;
    }
    __syncthreads();
    for (int e = threadIdx.x; e < 64 * 64; e += 256) {
        int a = e >> 6, n = e & 63;
        float tval = Ur[0][n];
        for (int d = 1; d < 32; ++d) {
            float ang = c0 * (float)(d * a);
            float cv, sv;
            sincosf(ang, &sv, &cv);
            tval += 2.f * (Ur[d][n] * cv - Ui[d][n] * sv);
        }
        T[lay * 4096 + e] = tval * (1.f / 64.f);
    }
}

/* ---------------- instance-norm stats ---------------- */
__global__ void pn_stats_kernel(const float* __restrict__ patches, float* __restrict__ mu,
                                float* __restrict__ rv) {
    int idx = blockIdx.x * 256 + threadIdx.x;
    int b = idx >> 10;
    int np = idx & 1023;
    const float* pp = patches + (size_t)b * 21504 + np;
    float s = 0.f, s2 = 0.f;
#pragma unroll
    for (int m = 0; m < MM; ++m) { float v = pp[m * 1024]; s += v; s2 += v * v; }
    float m0 = s * (1.f / MM);
    float var = s2 * (1.f / MM) - m0 * m0;
    mu[idx] = m0;
    rv[idx] = rsqrtf(var + EPSF);
}

/* ---------------- spectral mixing ---------------- */
__global__ void spect_kernel(const float* __restrict__ patches, const float* __restrict__ mu,
                             const float* __restrict__ rv, const float* __restrict__ g,
                             const float* __restrict__ be, const float* __restrict__ T,
                             float* __restrict__ ad) {
    int idx = blockIdx.x * 256 + threadIdx.x;
    int p = idx & 15;
    int a = (idx >> 4) & 63;
    int bm = idx >> 10;
    int m = bm % MM;
    int b = bm / MM;
    float gm = g[m], bm_ = be[m];
    const float* pp  = patches + (size_t)bm * 1024 + p;
    const float* mup = mu + b * 1024 + p;
    const float* rvp = rv + b * 1024 + p;
    const float* Tp  = T + a * 64;
    float acc = 0.f;
#pragma unroll 8
    for (int n = 0; n < 64; ++n) {
        float pn = (pp[n * 16] - mup[n * 16]) * rvp[n * 16] * gm + bm_;
        acc += Tp[n] * pn;
    }
    ad[idx] = acc;
}

/* ---------------- embeddings ---------------- */
template<int ADD>
__global__ __launch_bounds__(256) void embed_kernel(const float* __restrict__ src,
                                                    const float* __restrict__ Hin,
                                                    const float* __restrict__ inw,
                                                    const float* __restrict__ inb,
                                                    float* __restrict__ out32,
                                                    __half* __restrict__ out16) {
    __shared__ float ps[1024];
    int blk = blockIdx.x;
    int t = threadIdx.x;
    const float4* sp = (const float4*)(src + (size_t)blk * 1024);
    ((float4*)ps)[t] = sp[t];
    float w[3][16], bb[3];
#pragma unroll
    for (int j = 0; j < 3; ++j) {
        int c = t + 256 * j;
        bb[j] = inb[c];
#pragma unroll
        for (int p4 = 0; p4 < 4; ++p4) {
            float4 wv = *(const float4*)(inw + (size_t)c * 16 + p4 * 4);
            w[j][p4 * 4] = wv.x; w[j][p4 * 4 + 1] = wv.y; w[j][p4 * 4 + 2] = wv.z; w[j][p4 * 4 + 3] = wv.w;
        }
    }
    __syncthreads();
    size_t rowbase = (size_t)blk * 64 * DD;
    for (int r = 0; r < 64; ++r) {
        float pr[16];
#pragma unroll
        for (int p4 = 0; p4 < 4; ++p4) {
            float4 pv = *(const float4*)&ps[r * 16 + p4 * 4];
            pr[p4 * 4] = pv.x; pr[p4 * 4 + 1] = pv.y; pr[p4 * 4 + 2] = pv.z; pr[p4 * 4 + 3] = pv.w;
        }
        size_t ro = rowbase + (size_t)r * DD;
#pragma unroll
        for (int j = 0; j < 3; ++j) {
            float acc = bb[j];
            if (ADD) acc += Hin[ro + t + 256 * j];
#pragma unroll
            for (int p = 0; p < 16; ++p) acc = fmaf(pr[p], w[j][p], acc);
            out32[ro + t + 256 * j] = acc;
            if (ADD) out16[ro + t + 256 * j] = __float2half(acc);
        }
    }
}

/* ---------------- batchnorm ---------------- */
__global__ void zero_kernel(float* __restrict__ p, int n) {
    int idx = blockIdx.x * 256 + threadIdx.x;
    if (idx < n) p[idx] = 0.f;
}

__global__ void bn_reduce_kernel(const float* __restrict__ X, float* __restrict__ sum,
                                 float* __restrict__ sq) {
    int r0 = blockIdx.x * 128;
    float s[3] = {0.f, 0.f, 0.f}, q[3] = {0.f, 0.f, 0.f};
    for (int r = 0; r < 128; ++r) {
        const float* xp = X + (size_t)(r0 + r) * DD;
#pragma unroll
        for (int j = 0; j < 3; ++j) {
            float v = xp[threadIdx.x + j * 256];
            s[j] += v; q[j] += v * v;
        }
    }
#pragma unroll
    for (int j = 0; j < 3; ++j) {
        atomicAdd(&sum[threadIdx.x + j * 256], s[j]);
        atomicAdd(&sq[threadIdx.x + j * 256], q[j]);
    }
}

template<int WH>
__global__ void bn_apply_kernel(float* __restrict__ X, const float* __restrict__ sum,
                                const float* __restrict__ sq, const float* __restrict__ g,
                                const float* __restrict__ be, __half* __restrict__ Xh) {
    int idx = blockIdx.x * 256 + threadIdx.x;
    int c = idx % DD;
    const float inv_n = 1.f / (float)ROWS;
    float mean = sum[c] * inv_n;
    float var = sq[c] * inv_n - mean * mean;
    float v = (X[idx] - mean) * rsqrtf(var + EPSF) * g[c] + be[c];
    X[idx] = v;
    if (WH) Xh[idx] = __float2half(v);
}

/* fused bn2 + final norm (layer 3) */
__global__ void bn_apply_final_kernel(float* __restrict__ X, const float* __restrict__ sum,
                                      const float* __restrict__ sq,
                                      const float* __restrict__ g2, const float* __restrict__ b2,
                                      const float* __restrict__ g3, const float* __restrict__ b3) {
    int idx = blockIdx.x * 256 + threadIdx.x;
    int c = idx % DD;
    const float inv_n = 1.f / (float)ROWS;
    float mean = sum[c] * inv_n;
    float var = sq[c] * inv_n - mean * mean;
    float r = rsqrtf(var + EPSF);
    float s = g2[c] * r;
    float xv = (X[idx] - mean) * s;
    float r2 = rsqrtf(s * s * var + EPSF);
    X[idx] = xv * r2 * g3[c] + b3[c];
}

/* ---------------- final projection ---------------- */
__global__ void final_gemm_kernel(const float* __restrict__ hbuf, const float* __restrict__ ow,
                                  float* __restrict__ osmall) {
    __shared__ float hs[8 * 1024];
    int row0 = blockIdx.x * 8;
    int k0 = blockIdx.y * 1024;
    for (int j = threadIdx.x; j < 2048; j += 128) {
        int r = j >> 8, kq = j & 255;
        *(float4*)&hs[r * 1024 + kq * 4] =
            *(const float4*)&hbuf[(size_t)(row0 + r) * 49152 + k0 + kq * 4];
    }
    __syncthreads();
    int p = threadIdx.x;
    if (p < PREDN) {
        float acc[8] = {0.f, 0.f, 0.f, 0.f, 0.f, 0.f, 0.f, 0.f};
        const float* wp = ow + (size_t)p * 49152 + k0;
        for (int kq = 0; kq < 256; ++kq) {
            float4 w4 = *(const float4*)(wp + kq * 4);
#pragma unroll
            for (int r = 0; r < 8; ++r) {
                const float* hr = &hs[r * 1024 + kq * 4];
                acc[r] += hr[0] * w4.x + hr[1] * w4.y + hr[2] * w4.z + hr[3] * w4.w;
            }
        }
#pragma unroll
        for (int r = 0; r < 8; ++r) atomicAdd(&osmall[(row0 + r) * PREDN + p], acc[r]);
    }
}

/* ---------------- de-norm ---------------- */
__global__ void denorm_kernel(const float* __restrict__ osmall, const float* __restrict__ outb,
                              const float* __restrict__ rw, const float* __restrict__ rb,
                              const float* __restrict__ mean, const float* __restrict__ stdv,
                              float* __restrict__ out) {
    int idx = blockIdx.x * 256 + threadIdx.x;
    int m = idx % MM;
    int pr = (idx / MM) % PREDN;
    int b = idx / (MM * PREDN);
    int bm = b * MM + m;
    float v = osmall[bm * PREDN + pr] + outb[pr];
    v = (v - rb[m]) / (rw[m] + 1e-10f);
    out[idx] = v * stdv[bm] + mean[bm];
}

/* ---------------- launcher ---------------- */
extern "C" void kernel_launch(void* const* d_in, const int* in_sizes, int n_in,
                              void* d_out, int out_size) {
    const float* x         = (const float*)d_in[0];
    const float* attn_bias = (const float*)d_in[1];
    const float* revin_w   = (const float*)d_in[2];
    const float* revin_b   = (const float*)d_in[3];
    const float* in_w      = (const float*)d_in[4];
    const float* in_b      = (const float*)d_in[5];
    const float* ln1_g     = (const float*)d_in[6];
    const float* ln1_b     = (const float*)d_in[7];
    const float* spect_wr  = (const float*)d_in[8];
    const float* spect_wi  = (const float*)d_in[9];
    const float* Wq        = (const float*)d_in[10];
    const float* bq        = (const float*)d_in[11];
    const float* Wk        = (const float*)d_in[12];
    const float* bk        = (const float*)d_in[13];
    const float* Wv        = (const float*)d_in[14];
    const float* bv        = (const float*)d_in[15];
    const float* Wo        = (const float*)d_in[16];
    const float* bo        = (const float*)d_in[17];
    const float* c1_w      = (const float*)d_in[18];
    const float* c1_b      = (const float*)d_in[19];
    const float* c2_w      = (const float*)d_in[20];
    const float* c2_b      = (const float*)d_in[21];
    const float* bn1_g     = (const float*)d_in[22];
    const float* bn1_b     = (const float*)d_in[23];
    const float* bn2_g     = (const float*)d_in[24];
    const float* bn2_b     = (const float*)d_in[25];
    const float* norm_g    = (const float*)d_in[26];
    const float* norm_b    = (const float*)d_in[27];
    const float* out_w     = (const float*)d_in[28];
    const float* out_b     = (const float*)d_in[29];

    float* base = nullptr;
    cudaGetSymbolAddress((void**)&base, g_buf);
    float* mean   = base + OFF_MEAN;
    float* stdv   = base + OFF_STD;
    float* patch  = base + OFF_PATCH;
    float* Tm     = base + OFF_T;
    float* mu     = base + OFF_MU;
    float* rv     = base + OFF_RV;
    float* ad     = base + OFF_AD;
    float* bnsum  = base + OFF_BNSUM;
    float* bnsq   = base + OFF_BNSQ;
    float* osmall = base + OFF_OSMALL;
    float* h      = base + OFF_H;
    float* y      = base + OFF_Y;
    __half* qkvh  = (__half*)(base + OFF_QKVH);
    __half* y16   = (__half*)(base + OFF_Y16);
    __half* o16   = (__half*)(base + OFF_O16);
    __half* f4h   = (__half*)(base + OFF_F4H);
    __half* wh    = (__half*)(base + OFF_WH);
    __half* WHqkv = wh;
    __half* WHo   = wh + 5308416u;
    __half* WH1   = wh + 7077888u;
    __half* WH2   = wh + 14155776u;
    float* bqkv   = base + OFF_BQKV;

    cudaFuncSetAttribute(hgemm<0, 0, 1>, cudaFuncAttributeMaxDynamicSharedMemorySize, GSMH);
    cudaFuncSetAttribute(hgemm<0, 1, 0>, cudaFuncAttributeMaxDynamicSharedMemorySize, GSMH);
    cudaFuncSetAttribute(hgemm<1, 0, 1>, cudaFuncAttributeMaxDynamicSharedMemorySize, GSMH);

    const int TPB = 256;
    const int G_ED = (ROWS * DD) / TPB;

    wconv_qkv_h_kernel<<<1769472 / TPB, TPB>>>(Wq, WHqkv, 0);
    wconv_qkv_h_kernel<<<1769472 / TPB, TPB>>>(Wk, WHqkv, 1);
    wconv_qkv_h_kernel<<<1769472 / TPB, TPB>>>(Wv, WHqkv, 2);
    wconv_h_kernel<<<1769472 / TPB, TPB>>>(Wo, WHo, 1769472);
    wconv_h_kernel<<<7077888 / TPB, TPB>>>(c1_w, WH1, 7077888);
    wconv_h_kernel<<<7077888 / TPB, TPB>>>(c2_w, WH2, 7077888);
    bpack_kernel<<<27, TPB>>>(bq, bk, bv, bqkv);

    revin_stats_kernel<<<BMC, TPB>>>(x, mean, stdv);
    patches_kernel<<<344064 / TPB, TPB>>>(x, mean, stdv, revin_w, revin_b, patch);
    computeT_kernel<<<NLAYER, TPB>>>(spect_wr, spect_wi, Tm);
    embed_kernel<0><<<BMC, TPB>>>(patch, nullptr, in_w, in_b, h, nullptr);

    dim3 gQKV(QKVS / 128, ROWS / 128);
    dim3 gP(DD / 128, ROWS / 128);
    dim3 gF1(FF4 / 128, ROWS / 128);
    dim3 gFA(BMC, HH);

    for (int i = 0; i < NLAYER; ++i) {
        pn_stats_kernel<<<16384 / TPB, TPB>>>(patch, mu, rv);
        spect_kernel<<<344064 / TPB, TPB>>>(patch, mu, rv, ln1_g + i * MM, ln1_b + i * MM,
                                            Tm + i * 4096, ad);
        embed_kernel<1><<<BMC, TPB>>>(ad, h, in_w, in_b, y, y16);

        hgemm<0, 0, 1><<<gQKV, 128, GSMH>>>(y16, WHqkv + (size_t)i * 1769472u,
                                            bqkv + i * QKVS, nullptr, qkvh, ROWS, QKVS, DD);

        flash_attn_kernel<<<gFA, 128>>>(qkvh, attn_bias, o16);

        hgemm<0, 1, 0><<<gP, 128, GSMH>>>(o16, WHo + (size_t)i * DD * DD, bo + i * DD,
                                          y, y, ROWS, DD, DD);

        zero_kernel<<<6, TPB>>>(bnsum, 1536);
        bn_reduce_kernel<<<ROWS / 128, TPB>>>(y, bnsum, bnsq);
        bn_apply_kernel<1><<<G_ED, TPB>>>(y, bnsum, bnsq, bn1_g + i * DD, bn1_b + i * DD, y16);

        hgemm<1, 0, 1><<<gF1, 128, GSMH>>>(y16, WH1 + (size_t)i * FF4 * DD, c1_b + i * FF4,
                                           nullptr, f4h, ROWS, FF4, DD);
        hgemm<0, 1, 0><<<gP, 128, GSMH>>>(f4h, WH2 + (size_t)i * DD * FF4, c2_b + i * DD,
                                          y, h, ROWS, DD, FF4);

        zero_kernel<<<6, TPB>>>(bnsum, 1536);
        bn_reduce_kernel<<<ROWS / 128, TPB>>>(h, bnsum, bnsq);
        if (i < NLAYER - 1) {
            bn_apply_kernel<0><<<G_ED, TPB>>>(h, bnsum, bnsq, bn2_g + i * DD, bn2_b + i * DD, nullptr);
        } else {
            bn_apply_final_kernel<<<G_ED, TPB>>>(h, bnsum, bnsq, bn2_g + i * DD, bn2_b + i * DD,
                                                 norm_g, norm_b);
        }
    }

    zero_kernel<<<32256 / TPB, TPB>>>(osmall, 32256);
    final_gemm_kernel<<<dim3(BMC / 8, 48), 128>>>(h, out_w, osmall);
    denorm_kernel<<<32256 / TPB, TPB>>>(osmall, out_b, revin_w, revin_b, mean, stdv,
                                        (float*)d_out);
}